// round 7
// baseline (speedup 1.0000x reference)
#include <cuda_runtime.h>
#include <cuda_bf16.h>
#include <math.h>
#include <stdint.h>

#define BSZ 4
#define NV  4096
#define NP1 1024
#define NP2 256
#define KNN 32
typedef __nv_bfloat16 bf16;

// ---------------- scratch (device globals; no allocation allowed) ------------
__device__ int   g_nb1[BSZ*NV*KNN];
__device__ int   g_nb2[BSZ*NP1*KNN];
__device__ int   g_nb3[BSZ*NP2*KNN];
__device__ int   g_nbp[BSZ*NP1*4];
__device__ int   g_near1[BSZ*NV];
__device__ int   g_near2[BSZ*NV];
__device__ float g_fm0[BSZ*NV*128];
__device__ float g_fm1[BSZ*NV*128];
__device__ float g_f  [BSZ*NV*256];
__device__ float g_vp1[BSZ*NP1*3];
__device__ float g_fmp1[BSZ*NP1*128];
__device__ float g_fm2[BSZ*NP1*256];
__device__ float g_fm3[BSZ*NP1*256];
__device__ float g_vp2[BSZ*NP2*3];
__device__ float g_fmp2[BSZ*NP2*256];
__device__ float g_fm4[BSZ*NP2*512];
__device__ float g_fglob[BSZ*512];
__device__ float g_h2[BSZ*NV*512];
// bf16 split buffers (tensor-core GEMM operands)
__device__ __align__(256) bf16 g_fusehi[BSZ*NV*1792];
__device__ __align__(256) bf16 g_fuselo[BSZ*NV*1792];
__device__ __align__(256) bf16 g_h1hi[BSZ*NV*512];
__device__ __align__(256) bf16 g_h1lo[BSZ*NV*512];
__device__ __align__(256) bf16 g_cw1hi[512*1792];
__device__ __align__(256) bf16 g_cw1lo[512*1792];
__device__ __align__(256) bf16 g_cw2hi[512*512];
__device__ __align__(256) bf16 g_cw2lo[512*512];
__device__ __align__(256) bf16 g_fm0hi[BSZ*NV*128];
__device__ __align__(256) bf16 g_fm0lo[BSZ*NV*128];
__device__ __align__(256) bf16 g_fmp1hi[BSZ*NP1*128];
__device__ __align__(256) bf16 g_fmp1lo[BSZ*NP1*128];
__device__ __align__(256) bf16 g_fm2hi[BSZ*NP1*256];
__device__ __align__(256) bf16 g_fm2lo[BSZ*NP1*256];
__device__ __align__(256) bf16 g_fmp2hi[BSZ*NP2*256];
__device__ __align__(256) bf16 g_fmp2lo[BSZ*NP2*256];
__device__ __align__(256) bf16 g_w1thi[256*128];
__device__ __align__(256) bf16 g_w1tlo[256*128];
__device__ __align__(256) bf16 g_w2thi[512*128];
__device__ __align__(256) bf16 g_w2tlo[512*128];
__device__ __align__(256) bf16 g_w3thi[512*256];
__device__ __align__(256) bf16 g_w3tlo[512*256];
__device__ __align__(256) bf16 g_w4thi[1024*256];
__device__ __align__(256) bf16 g_w4tlo[1024*256];
// pre-normalized direction vectors
__device__ float g_dn0[3*128];
__device__ float g_dn1[3*128];
__device__ float g_dn2[3*256];
__device__ float g_dn3[3*256];
__device__ float g_dn4[3*512];

// ---------------- PTX helpers (arch-agnostic: sm_80-era instructions) --------
__device__ __forceinline__ uint32_t smem_u32(const void* p){
    uint32_t a;
    asm("{ .reg .u64 t; cvta.to.shared.u64 t, %1; cvt.u32.u64 %0, t; }" : "=r"(a) : "l"(p));
    return a;
}
#define CP_ASYNC16(dst, src) \
    asm volatile("cp.async.ca.shared.global [%0], [%1], 16;" :: "r"(dst), "l"(src) : "memory")
#define CP_COMMIT() asm volatile("cp.async.commit_group;" ::: "memory")
#define CP_WAIT(n)  asm volatile("cp.async.wait_group %0;" :: "n"(n) : "memory")
#define LDSM_X4(r, a) \
    asm volatile("ldmatrix.sync.aligned.m8n8.x4.shared.b16 {%0,%1,%2,%3}, [%4];" \
        : "=r"((r)[0]),"=r"((r)[1]),"=r"((r)[2]),"=r"((r)[3]) : "r"(a))
#define LDSM_X2(r, a) \
    asm volatile("ldmatrix.sync.aligned.m8n8.x2.shared.b16 {%0,%1}, [%2];" \
        : "=r"((r)[0]),"=r"((r)[1]) : "r"(a))
#define MMA_BF16(d, a, b) \
    asm volatile("mma.sync.aligned.m16n8k16.row.col.f32.bf16.bf16.f32 " \
        "{%0,%1,%2,%3}, {%4,%5,%6,%7}, {%8,%9}, {%0,%1,%2,%3};" \
        : "+f"((d)[0]),"+f"((d)[1]),"+f"((d)[2]),"+f"((d)[3]) \
        : "r"((a)[0]),"r"((a)[1]),"r"((a)[2]),"r"((a)[3]), "r"((b)[0]),"r"((b)[1]))

// ---------------- split fp32 -> bf16 hi/lo -----------------------------------
__global__ void split_kernel(const float* __restrict__ src,
                             bf16* __restrict__ hi, bf16* __restrict__ lo, int n)
{
    int i = blockIdx.x*256 + threadIdx.x;
    if (i < n) {
        float v = src[i];
        bf16 h = __float2bfloat16(v);
        hi[i] = h;
        lo[i] = __float2bfloat16(v - __bfloat162float(h));
    }
}

// ---------------- transpose-split: w (K,N) -> wT hi/lo (N,K) -----------------
__global__ void tsplit_kernel(const float* __restrict__ w, int K, int N,
                              bf16* __restrict__ hi, bf16* __restrict__ lo)
{
    int n = blockIdx.x;
    for (int k = threadIdx.x; k < K; k += blockDim.x) {
        float v = w[(size_t)k*N + n];
        bf16 h = __float2bfloat16(v);
        hi[(size_t)n*K + k] = h;
        lo[(size_t)n*K + k] = __float2bfloat16(v - __bfloat162float(h));
    }
}

// ---------------- normalize direction vectors (3,C) once ---------------------
__global__ void ndirs_kernel(const float* __restrict__ d, float* __restrict__ o, int C)
{
    int c = blockIdx.x*128 + threadIdx.x;
    if (c < C) {
        float x = d[c], y = d[C+c], z = d[2*C+c];
        float n = sqrtf(x*x + y*y + z*z);
        float inv = 1.0f / fmaxf(n, 1e-12f);
        o[c] = x*inv; o[C+c] = y*inv; o[2*C+c] = z*inv;
    }
}

// ================= warp-MMA GEMM: C(128x128 tile) = A @ B^T + bias ===========
// A: (M,K) bf16 hi/lo row-major.  B: (N,K) bf16 hi/lo row-major.
// Split: D = Ah@Bh + Ah@Bl + Al@Bh  (fp32 accum).
#define MMA_SMEM_TOTAL (2*65536)
template<int KTOT, bool RELU, bool OUT_SPLIT>
__global__ __launch_bounds__(256, 1)
void mma_gemm(const bf16* __restrict__ Ahi, const bf16* __restrict__ Alo,
              const bf16* __restrict__ Bhi, const bf16* __restrict__ Blo,
              const float* __restrict__ bias, int Nstride,
              float* __restrict__ Cf, bf16* __restrict__ Chi, bf16* __restrict__ Clo)
{
    extern __shared__ __align__(1024) char smem[];
    const uint32_t sbase = smem_u32(smem);
    const int tid  = threadIdx.x;
    const int lane = tid & 31, warp = tid >> 5;
    const int m0 = blockIdx.y * 128, n0 = blockIdx.x * 128;
    const int wm = (warp >> 2) * 64, wn = (warp & 3) * 32;

    const int      lr0  = tid >> 3;
    const uint32_t lc16 = (tid & 7) * 16;
    const int      lcel = (tid & 7) * 8;

    const bf16* srcs[4] = { Ahi + (size_t)m0*KTOT, Alo + (size_t)m0*KTOT,
                            Bhi + (size_t)n0*KTOT, Blo + (size_t)n0*KTOT };

    float acc[4][4][4];
#pragma unroll
    for (int mi=0;mi<4;mi++)
#pragma unroll
        for (int ni=0;ni<4;ni++)
#pragma unroll
            for (int q=0;q<4;q++) acc[mi][ni][q]=0.f;

    const int NCH = KTOT / 64;

    {
        const size_t kb = lcel;
#pragma unroll
        for (int b=0;b<4;b++)
#pragma unroll
            for (int it=0;it<4;it++) {
                const int row = lr0 + it*32;
                const uint32_t dst = sbase + b*16384u + row*128u + (lc16 ^ ((row&7)<<4));
                CP_ASYNC16(dst, (const void*)(srcs[b] + (size_t)row*KTOT + kb));
            }
        CP_COMMIT();
    }

    const int      arow_in = (lane & 7) + (lane & 8);
    const uint32_t abyte   = (lane & 16) ? 16u : 0u;
    const int      brow_in = lane & 7;
    const uint32_t bbyte   = (lane & 8) ? 16u : 0u;

    for (int i=0;i<NCH;i++) {
        if (i+1 < NCH) {
            const uint32_t sb = sbase + ((i+1)&1)*65536u;
            const size_t kb = (size_t)(i+1)*64 + lcel;
#pragma unroll
            for (int b=0;b<4;b++)
#pragma unroll
                for (int it=0;it<4;it++) {
                    const int row = lr0 + it*32;
                    const uint32_t dst = sb + b*16384u + row*128u + (lc16 ^ ((row&7)<<4));
                    CP_ASYNC16(dst, (const void*)(srcs[b] + (size_t)row*KTOT + kb));
                }
            CP_COMMIT();
            CP_WAIT(1);
        } else {
            CP_WAIT(0);
        }
        __syncthreads();

        const uint32_t sb = sbase + (i&1)*65536u;
#pragma unroll
        for (int kk=0;kk<4;kk++) {
            const uint32_t kbb = kk*32u;
            uint32_t ah[4][4], al[4][4], bhf[4][2], blf[4][2];
#pragma unroll
            for (int mi=0;mi<4;mi++) {
                const int row = wm + mi*16 + arow_in;
                const uint32_t off = row*128u + ((kbb + abyte) ^ ((row&7)<<4));
                LDSM_X4(ah[mi], sb + off);
                LDSM_X4(al[mi], sb + 16384u + off);
            }
#pragma unroll
            for (int ni=0;ni<4;ni++) {
                const int row = wn + ni*8 + brow_in;
                const uint32_t off = row*128u + ((kbb + bbyte) ^ ((row&7)<<4));
                LDSM_X2(bhf[ni], sb + 32768u + off);
                LDSM_X2(blf[ni], sb + 49152u + off);
            }
#pragma unroll
            for (int mi=0;mi<4;mi++)
#pragma unroll
                for (int ni=0;ni<4;ni++) {
                    MMA_BF16(acc[mi][ni], ah[mi], bhf[ni]);
                    MMA_BF16(acc[mi][ni], ah[mi], blf[ni]);
                    MMA_BF16(acc[mi][ni], al[mi], bhf[ni]);
                }
        }
        __syncthreads();
    }

#pragma unroll
    for (int mi=0;mi<4;mi++) {
        const int r0g = m0 + wm + mi*16 + (lane>>2);
#pragma unroll
        for (int ni=0;ni<4;ni++) {
            const int col = n0 + wn + ni*8 + (lane&3)*2;
            const float b0 = bias[col], b1 = bias[col+1];
            float v0 = acc[mi][ni][0] + b0, v1 = acc[mi][ni][1] + b1;
            float v2 = acc[mi][ni][2] + b0, v3 = acc[mi][ni][3] + b1;
            if (RELU) {
                v0 = fmaxf(v0,0.f); v1 = fmaxf(v1,0.f);
                v2 = fmaxf(v2,0.f); v3 = fmaxf(v3,0.f);
            }
            const size_t g0 = (size_t)r0g*Nstride + col;
            const size_t g1 = (size_t)(r0g+8)*Nstride + col;
            if (OUT_SPLIT) {
                bf16 h0 = __float2bfloat16(v0), h1 = __float2bfloat16(v1);
                bf16 h2b = __float2bfloat16(v2), h3 = __float2bfloat16(v3);
                Chi[g0] = h0; Chi[g0+1] = h1;
                Chi[g1] = h2b; Chi[g1+1] = h3;
                Clo[g0]   = __float2bfloat16(v0 - __bfloat162float(h0));
                Clo[g0+1] = __float2bfloat16(v1 - __bfloat162float(h1));
                Clo[g1]   = __float2bfloat16(v2 - __bfloat162float(h2b));
                Clo[g1+1] = __float2bfloat16(v3 - __bfloat162float(h3));
            } else {
                float2 p0 = make_float2(v0, v1), p1 = make_float2(v2, v3);
                *(float2*)&Cf[g0] = p0;
                *(float2*)&Cf[g1] = p1;
            }
        }
    }
}

// ---------------- KNN: brute force, branch-free register top-K ---------------
template<int K>
__global__ void knn_kernel(const float* __restrict__ verts,
                           const int* __restrict__ qidx, // null => identity
                           int nq, int V, int* __restrict__ out)
{
    int b = blockIdx.y;
    int q = blockIdx.x * 128 + threadIdx.x;
    const float* vb = verts + (size_t)b * V * 3;
    bool active = q < nq;
    int self = -1;
    float qx=0.f, qy=0.f, qz=0.f, qa2=0.f;
    if (active) {
        self = qidx ? qidx[q] : q;
        qx = vb[self*3+0]; qy = vb[self*3+1]; qz = vb[self*3+2];
        qa2 = qx*qx + qy*qy + qz*qz;
    }
    float dk[K]; int ik[K];
#pragma unroll
    for (int i=0;i<K;i++){ dk[i]=3.4e38f; ik[i]=0; }
    float worst = 3.4e38f;
    int   wpos  = 0;

    __shared__ float4 sp[128];
    for (int t0=0; t0<V; t0+=128) {
        int j = t0 + threadIdx.x;
        float x = vb[j*3+0], y = vb[j*3+1], z = vb[j*3+2];
        sp[threadIdx.x] = make_float4(x,y,z, x*x+y*y+z*z);
        __syncthreads();
        if (active) {
#pragma unroll 4
            for (int jj=0; jj<128; jj++) {
                float4 p = sp[jj];
                float d = qa2 + p.w - 2.0f*(qx*p.x + qy*p.y + qz*p.z);
                int gj = t0 + jj;
                if (d < worst && gj != self) {
                    float w = -3.4e38f; int wp = 0;
#pragma unroll
                    for (int i=0;i<K;i++) {
                        if (i == wpos) { dk[i] = d; ik[i] = gj; }
                        if (dk[i] > w) { w = dk[i]; wp = i; }
                    }
                    worst = w; wpos = wp;
                }
            }
        }
        __syncthreads();
    }
    if (active) {
        int* o = out + ((size_t)b*nq + q)*K;
#pragma unroll
        for (int i=0;i<K;i++) o[i]=ik[i];
    }
}

// ---------------- conv_surface (fm0) ----------------------------------------
__global__ void conv_surface_kernel(const float* __restrict__ verts,
                                    const int* __restrict__ nb,
                                    const float* __restrict__ dn0,
                                    float* __restrict__ fm0)
{
    int bv = blockIdx.x;
    int b = bv >> 12, v = bv & (NV-1);
    const float* vb = verts + (size_t)b*NV*3;
    __shared__ float sdx[KNN], sdy[KNN], sdz[KNN];
    int t = threadIdx.x;
    float cx = vb[v*3+0], cy = vb[v*3+1], cz = vb[v*3+2];
    if (t < KNN) {
        int j = nb[(size_t)bv*KNN + t];
        float dx = vb[j*3+0]-cx, dy = vb[j*3+1]-cy, dz = vb[j*3+2]-cz;
        float n = sqrtf(dx*dx+dy*dy+dz*dz);
        float inv = 1.0f / fmaxf(n, 1e-12f);
        sdx[t]=dx*inv; sdy[t]=dy*inv; sdz[t]=dz*inv;
    }
    __syncthreads();
    int k = t;
    float d0 = dn0[k], d1 = dn0[128+k], d2 = dn0[256+k];
    float m = 0.0f;
#pragma unroll
    for (int j=0;j<KNN;j++)
        m = fmaxf(m, sdx[j]*d0 + sdy[j]*d1 + sdz[j]*d2);
    fm0[(size_t)bv*128 + k] = m;
}

// ---------------- conv_layer epilogue (dirs prenormalized) -------------------
template<int COUT, bool RELU>
__global__ void conv_layer_kernel(const float* __restrict__ verts, int V,
                                  const int* __restrict__ nb,
                                  const float* __restrict__ f,
                                  const float* __restrict__ dn,
                                  float* __restrict__ out)
{
    int bv = blockIdx.x;
    int b = bv / V, v = bv - b*V;
    const float* vb = verts + (size_t)b*V*3;
    __shared__ float sdx[KNN], sdy[KNN], sdz[KNN];
    __shared__ int   si[KNN];
    int t = threadIdx.x;
    float cx = vb[v*3+0], cy = vb[v*3+1], cz = vb[v*3+2];
    if (t < KNN) {
        int j = nb[(size_t)bv*KNN + t];
        si[t] = j;
        float dx = vb[j*3+0]-cx, dy = vb[j*3+1]-cy, dz = vb[j*3+2]-cz;
        float n = sqrtf(dx*dx+dy*dy+dz*dz);
        float inv = 1.0f / fmaxf(n, 1e-12f);
        sdx[t]=dx*inv; sdy[t]=dy*inv; sdz[t]=dz*inv;
    }
    __syncthreads();
    const float* fb = f + (size_t)b*V*(2*COUT);
    for (int co = t; co < COUT; co += blockDim.x) {
        float d0 = dn[co], d1 = dn[COUT+co], d2 = dn[2*COUT+co];
        float m = -3.4e38f;
#pragma unroll 8
        for (int j=0;j<KNN;j++) {
            float th = fmaxf(sdx[j]*d0 + sdy[j]*d1 + sdz[j]*d2, 0.0f);
            float val = th * fb[si[j]*(2*COUT) + COUT + co];
            m = fmaxf(m, val);
        }
        float r = fb[v*(2*COUT) + co] + m;
        out[((size_t)b*V+v)*COUT + co] = RELU ? fmaxf(r, 0.0f) : r;
    }
}

// ---------------- pool ------------------------------------------------------
__global__ void pool_kernel(const float* __restrict__ verts,
                            const float* __restrict__ fm,
                            int V, int C,
                            const int* __restrict__ sidx,
                            const int* __restrict__ nb4, int ns,
                            float* __restrict__ vout, float* __restrict__ fout)
{
    int bq = blockIdx.x;
    int b = bq / ns, q = bq - b*ns;
    int t = threadIdx.x;
    int sv = sidx[q];
    if (t < 3) vout[(size_t)bq*3 + t] = verts[((size_t)b*V + sv)*3 + t];
    const int* nbq = nb4 + (size_t)bq*4;
    int j0=nbq[0], j1=nbq[1], j2=nbq[2], j3=nbq[3];
    const float* fb = fm + (size_t)b*V*C;
    for (int c=t; c<C; c+=blockDim.x) {
        float m = fmaxf(fmaxf(fb[j0*C+c], fb[j1*C+c]),
                        fmaxf(fb[j2*C+c], fb[j3*C+c]));
        fout[(size_t)bq*C + c] = m;
    }
}

// ---------------- nearest ---------------------------------------------------
__global__ void nearest_kernel(const float* __restrict__ verts,
                               const float* __restrict__ src,
                               int V, int S, int* __restrict__ out)
{
    int b = blockIdx.y;
    int q = blockIdx.x * 128 + threadIdx.x;
    const float* vb = verts + (size_t)b*V*3;
    const float* sb = src + (size_t)b*S*3;
    float qx = vb[q*3+0], qy = vb[q*3+1], qz = vb[q*3+2];
    float qa2 = qx*qx + qy*qy + qz*qz;
    float best = 3.4e38f; int bi = 0;
    __shared__ float4 sp[128];
    for (int t0=0; t0<S; t0+=128) {
        int j = t0 + threadIdx.x;
        float x = sb[j*3+0], y = sb[j*3+1], z = sb[j*3+2];
        sp[threadIdx.x] = make_float4(x,y,z, x*x+y*y+z*z);
        __syncthreads();
        for (int jj=0; jj<128; jj++) {
            float4 p = sp[jj];
            float d = qa2 + p.w - 2.0f*(qx*p.x + qy*p.y + qz*p.z);
            if (d < best) { best = d; bi = t0+jj; }
        }
        __syncthreads();
    }
    out[(size_t)b*V + q] = bi;
}

// ---------------- global feature --------------------------------------------
__global__ void fglobal_kernel(const float* __restrict__ fm4, float* __restrict__ g)
{
    int b = blockIdx.x, c = threadIdx.x;
    float m = -3.4e38f;
    for (int v=0; v<NP2; v++) m = fmaxf(m, fm4[((size_t)b*NP2+v)*512 + c]);
    g[(size_t)b*512 + c] = m;
}

// ---------------- fuse assembly -> bf16 hi/lo ---------------------------------
__global__ void fuse_kernel(const float* __restrict__ fm0, const float* __restrict__ fm1,
                            const float* __restrict__ fm2, const float* __restrict__ fm3,
                            const float* __restrict__ fm4, const float* __restrict__ fg,
                            const int* __restrict__ near1, const int* __restrict__ near2,
                            bf16* __restrict__ fhi, bf16* __restrict__ flo)
{
    int bv = blockIdx.x;
    int b = bv >> 12;
    int n1 = near1[bv], n2 = near2[bv];
    size_t o = (size_t)bv*1792;
    for (int c = threadIdx.x; c < 1792; c += blockDim.x) {
        float val;
        if (c < 128)        val = fm0[(size_t)bv*128 + c];
        else if (c < 256)   val = fm1[(size_t)bv*128 + (c-128)];
        else if (c < 512)   val = fm2[((size_t)b*NP1+n1)*256 + (c-256)];
        else if (c < 768)   val = fm3[((size_t)b*NP1+n1)*256 + (c-512)];
        else if (c < 1280)  val = fm4[((size_t)b*NP2+n2)*512 + (c-768)];
        else                val = fg [(size_t)b*512 + (c-1280)];
        bf16 h = __float2bfloat16(val);
        fhi[o+c] = h;
        flo[o+c] = __float2bfloat16(val - __bfloat162float(h));
    }
}

// ---------------- head: out(16 rows x 13) = h2 @ cw3^T + cb3 ----------------
__global__ void head_kernel(const float* __restrict__ h2,
                            const float* __restrict__ cw3,
                            const float* __restrict__ cb3,
                            float* __restrict__ out)
{
    __shared__ float sh[16][512];
    __shared__ float sw[13*513];
    const int tid = threadIdx.x;
    const int r = tid >> 4, c = tid & 15;
    const int row0 = blockIdx.x * 16;
    for (int i = tid; i < 16*512; i += 256)
        sh[i>>9][i&511] = h2[(size_t)row0*512 + i];
    for (int i = tid; i < 13*512; i += 256)
        sw[(i>>9)*513 + (i&511)] = cw3[i];
    __syncthreads();
    if (c < 13) {
        float acc = cb3[c];
        const float* w = &sw[c*513];
        const float* hrow = sh[r];
#pragma unroll 8
        for (int k=0;k<512;k++) acc += hrow[k]*w[k];
        out[(size_t)(row0+r)*13 + c] = acc;
    }
}

// -----------------------------------------------------------------------------
static void* sym_addr(const void* symbol) {
    void* p = nullptr;
    cudaGetSymbolAddress(&p, symbol);
    return p;
}

extern "C" void kernel_launch(void* const* d_in, const int* in_sizes, int n_in,
                              void* d_out, int out_size)
{
    (void)in_sizes; (void)n_in; (void)out_size;
    const float* vertices = (const float*)d_in[0];
    const int*   sidx1    = (const int*)  d_in[1];
    const int*   sidx2    = (const int*)  d_in[2];
    const float* dir0     = (const float*)d_in[3];
    const float* w1 = (const float*)d_in[4];  const float* b1 = (const float*)d_in[5];  const float* d1 = (const float*)d_in[6];
    const float* w2 = (const float*)d_in[7];  const float* b2 = (const float*)d_in[8];  const float* d2 = (const float*)d_in[9];
    const float* w3 = (const float*)d_in[10]; const float* b3 = (const float*)d_in[11]; const float* d3 = (const float*)d_in[12];
    const float* w4 = (const float*)d_in[13]; const float* b4 = (const float*)d_in[14]; const float* d4 = (const float*)d_in[15];
    const float* cw1 = (const float*)d_in[16]; const float* cb1 = (const float*)d_in[17];
    const float* cw2 = (const float*)d_in[18]; const float* cb2 = (const float*)d_in[19];
    const float* cw3 = (const float*)d_in[20]; const float* cb3 = (const float*)d_in[21];
    float* out = (float*)d_out;

    int*   nb1   = (int*)  sym_addr(g_nb1);
    int*   nb2   = (int*)  sym_addr(g_nb2);
    int*   nb3   = (int*)  sym_addr(g_nb3);
    int*   nbp   = (int*)  sym_addr(g_nbp);
    int*   near1 = (int*)  sym_addr(g_near1);
    int*   near2 = (int*)  sym_addr(g_near2);
    float* fm0   = (float*)sym_addr(g_fm0);
    float* fm1   = (float*)sym_addr(g_fm1);
    float* fbuf  = (float*)sym_addr(g_f);
    float* vp1   = (float*)sym_addr(g_vp1);
    float* fmp1  = (float*)sym_addr(g_fmp1);
    float* fm2   = (float*)sym_addr(g_fm2);
    float* fm3   = (float*)sym_addr(g_fm3);
    float* vp2   = (float*)sym_addr(g_vp2);
    float* fmp2  = (float*)sym_addr(g_fmp2);
    float* fm4   = (float*)sym_addr(g_fm4);
    float* fglob = (float*)sym_addr(g_fglob);
    float* h2    = (float*)sym_addr(g_h2);
    bf16* fusehi = (bf16*)sym_addr(g_fusehi);
    bf16* fuselo = (bf16*)sym_addr(g_fuselo);
    bf16* h1hi   = (bf16*)sym_addr(g_h1hi);
    bf16* h1lo   = (bf16*)sym_addr(g_h1lo);
    bf16* cw1hi  = (bf16*)sym_addr(g_cw1hi);
    bf16* cw1lo  = (bf16*)sym_addr(g_cw1lo);
    bf16* cw2hi  = (bf16*)sym_addr(g_cw2hi);
    bf16* cw2lo  = (bf16*)sym_addr(g_cw2lo);
    bf16* fm0hi  = (bf16*)sym_addr(g_fm0hi);   bf16* fm0lo  = (bf16*)sym_addr(g_fm0lo);
    bf16* fmp1hi = (bf16*)sym_addr(g_fmp1hi);  bf16* fmp1lo = (bf16*)sym_addr(g_fmp1lo);
    bf16* fm2hi  = (bf16*)sym_addr(g_fm2hi);   bf16* fm2lo  = (bf16*)sym_addr(g_fm2lo);
    bf16* fmp2hi = (bf16*)sym_addr(g_fmp2hi);  bf16* fmp2lo = (bf16*)sym_addr(g_fmp2lo);
    bf16* w1thi  = (bf16*)sym_addr(g_w1thi);   bf16* w1tlo  = (bf16*)sym_addr(g_w1tlo);
    bf16* w2thi  = (bf16*)sym_addr(g_w2thi);   bf16* w2tlo  = (bf16*)sym_addr(g_w2tlo);
    bf16* w3thi  = (bf16*)sym_addr(g_w3thi);   bf16* w3tlo  = (bf16*)sym_addr(g_w3tlo);
    bf16* w4thi  = (bf16*)sym_addr(g_w4thi);   bf16* w4tlo  = (bf16*)sym_addr(g_w4tlo);
    float* dn0 = (float*)sym_addr(g_dn0);
    float* dn1 = (float*)sym_addr(g_dn1);
    float* dn2 = (float*)sym_addr(g_dn2);
    float* dn3 = (float*)sym_addr(g_dn3);
    float* dn4 = (float*)sym_addr(g_dn4);

    cudaFuncSetAttribute(mma_gemm<1792,true,true>,  cudaFuncAttributeMaxDynamicSharedMemorySize, MMA_SMEM_TOTAL);
    cudaFuncSetAttribute(mma_gemm<512,true,false>,  cudaFuncAttributeMaxDynamicSharedMemorySize, MMA_SMEM_TOTAL);
    cudaFuncSetAttribute(mma_gemm<128,false,false>, cudaFuncAttributeMaxDynamicSharedMemorySize, MMA_SMEM_TOTAL);
    cudaFuncSetAttribute(mma_gemm<256,false,false>, cudaFuncAttributeMaxDynamicSharedMemorySize, MMA_SMEM_TOTAL);

    // idx0-1: weight splits
    split_kernel<<<(512*1792+255)/256, 256>>>(cw1, cw1hi, cw1lo, 512*1792);
    split_kernel<<<(512*512+255)/256, 256>>>(cw2, cw2hi, cw2lo, 512*512);
    // idx2: full-res KNN(32)
    knn_kernel<KNN><<<dim3(NV/128, BSZ), 128>>>(vertices, nullptr, NV, NV, nb1);
    // idx3: PROFILING PROBE — 1-CTA mma_gemm on stale data; h1hi tile is
    // overwritten by the real h1 GEMM below, so final output is unaffected.
    mma_gemm<1792,true,true><<<dim3(1,1), 256, MMA_SMEM_TOTAL>>>(
        fusehi, fuselo, cw1hi, cw1lo, cb1, 512, nullptr, h1hi, h1lo);
    // normalize dirs + transpose-split weights (tiny)
    ndirs_kernel<<<1, 128>>>(dir0, dn0, 128);
    ndirs_kernel<<<1, 128>>>(d1, dn1, 128);
    ndirs_kernel<<<2, 128>>>(d2, dn2, 256);
    ndirs_kernel<<<2, 128>>>(d3, dn3, 256);
    ndirs_kernel<<<4, 128>>>(d4, dn4, 512);
    tsplit_kernel<<<256, 128>>>(w1, 128, 256, w1thi, w1tlo);
    tsplit_kernel<<<512, 128>>>(w2, 128, 512, w2thi, w2tlo);
    tsplit_kernel<<<512, 256>>>(w3, 256, 512, w3thi, w3tlo);
    tsplit_kernel<<<1024, 256>>>(w4, 256, 1024, w4thi, w4tlo);
    // fm0 = conv_surface
    conv_surface_kernel<<<BSZ*NV, 128>>>(vertices, nb1, dn0, fm0);
    split_kernel<<<(BSZ*NV*128+255)/256, 256>>>(fm0, fm0hi, fm0lo, BSZ*NV*128);
    // fm1 = relu(conv_layer(fm0; w1,b1,d1; 128))
    mma_gemm<128,false,false><<<dim3(2, (BSZ*NV)/128), 256, MMA_SMEM_TOTAL>>>(
        fm0hi, fm0lo, w1thi, w1tlo, b1, 256, fbuf, nullptr, nullptr);
    conv_layer_kernel<128,true><<<BSZ*NV, 128>>>(vertices, NV, nb1, fbuf, dn1, fm1);
    // pool1
    knn_kernel<4><<<dim3(NP1/128, BSZ), 128>>>(vertices, sidx1, NP1, NV, nbp);
    pool_kernel<<<BSZ*NP1, 128>>>(vertices, fm1, NV, 128, sidx1, nbp, NP1, vp1, fmp1);
    split_kernel<<<(BSZ*NP1*128+255)/256, 256>>>(fmp1, fmp1hi, fmp1lo, BSZ*NP1*128);
    // KNN level 1
    knn_kernel<KNN><<<dim3(NP1/128, BSZ), 128>>>(vp1, nullptr, NP1, NP1, nb2);
    // fm2
    mma_gemm<128,false,false><<<dim3(4, (BSZ*NP1)/128), 256, MMA_SMEM_TOTAL>>>(
        fmp1hi, fmp1lo, w2thi, w2tlo, b2, 512, fbuf, nullptr, nullptr);
    conv_layer_kernel<256,true><<<BSZ*NP1, 256>>>(vp1, NP1, nb2, fbuf, dn2, fm2);
    split_kernel<<<(BSZ*NP1*256+255)/256, 256>>>(fm2, fm2hi, fm2lo, BSZ*NP1*256);
    // fm3
    mma_gemm<256,false,false><<<dim3(4, (BSZ*NP1)/128), 256, MMA_SMEM_TOTAL>>>(
        fm2hi, fm2lo, w3thi, w3tlo, b3, 512, fbuf, nullptr, nullptr);
    conv_layer_kernel<256,true><<<BSZ*NP1, 256>>>(vp1, NP1, nb2, fbuf, dn3, fm3);
    // pool2
    knn_kernel<4><<<dim3(NP2/128, BSZ), 128>>>(vp1, sidx2, NP2, NP1, nbp);
    pool_kernel<<<BSZ*NP2, 256>>>(vp1, fm3, NP1, 256, sidx2, nbp, NP2, vp2, fmp2);
    split_kernel<<<(BSZ*NP2*256+255)/256, 256>>>(fmp2, fmp2hi, fmp2lo, BSZ*NP2*256);
    // KNN level 2
    knn_kernel<KNN><<<dim3(NP2/128, BSZ), 128>>>(vp2, nullptr, NP2, NP2, nb3);
    // fm4
    mma_gemm<256,false,false><<<dim3(8, (BSZ*NP2)/128), 256, MMA_SMEM_TOTAL>>>(
        fmp2hi, fmp2lo, w4thi, w4tlo, b4, 1024, fbuf, nullptr, nullptr);
    conv_layer_kernel<512,false><<<BSZ*NP2, 256>>>(vp2, NP2, nb3, fbuf, dn4, fm4);
    // global max feature
    fglobal_kernel<<<BSZ, 512>>>(fm4, fglob);
    // nearest upsample indices
    nearest_kernel<<<dim3(NV/128, BSZ), 128>>>(vertices, vp1, NV, NP1, near1);
    nearest_kernel<<<dim3(NV/128, BSZ), 128>>>(vertices, vp2, NV, NP2, near2);
    // fuse -> bf16 hi/lo
    fuse_kernel<<<BSZ*NV, 256>>>(fm0, fm1, fm2, fm3, fm4, fglob, near1, near2, fusehi, fuselo);
    // h1 = relu(fuse @ cw1^T + cb1)
    mma_gemm<1792,true,true><<<dim3(4, (BSZ*NV)/128), 256, MMA_SMEM_TOTAL>>>(
        fusehi, fuselo, cw1hi, cw1lo, cb1, 512, nullptr, h1hi, h1lo);
    // h2 = relu(h1 @ cw2^T + cb2)
    mma_gemm<512,true,false><<<dim3(4, (BSZ*NV)/128), 256, MMA_SMEM_TOTAL>>>(
        h1hi, h1lo, cw2hi, cw2lo, cb2, 512, h2, nullptr, nullptr);
    // logits
    head_kernel<<<(BSZ*NV)/16, 256>>>(h2, cw3, cb3, out);
}

// round 8
// speedup vs baseline: 1.0211x; 1.0211x over previous
#include <cuda_runtime.h>
#include <cuda_bf16.h>
#include <math.h>
#include <stdint.h>

#define BSZ 4
#define NV  4096
#define NP1 1024
#define NP2 256
#define KNN 32
typedef __nv_bfloat16 bf16;

// ---------------- scratch (device globals; no allocation allowed) ------------
__device__ int   g_nb1[BSZ*NV*KNN];
__device__ int   g_nb2[BSZ*NP1*KNN];
__device__ int   g_nb3[BSZ*NP2*KNN];
__device__ int   g_nbp[BSZ*NP1*4];
__device__ int   g_near1[BSZ*NV];
__device__ int   g_near2[BSZ*NV];
__device__ float g_fm0[BSZ*NV*128];
__device__ float g_fm1[BSZ*NV*128];
__device__ float g_f  [BSZ*NV*256];
__device__ float g_vp1[BSZ*NP1*3];
__device__ float g_fmp1[BSZ*NP1*128];
__device__ float g_fm2[BSZ*NP1*256];
__device__ float g_fm3[BSZ*NP1*256];
__device__ float g_vp2[BSZ*NP2*3];
__device__ float g_fmp2[BSZ*NP2*256];
__device__ float g_fm4[BSZ*NP2*512];
__device__ float g_fglob[BSZ*512];
__device__ float g_h2[BSZ*NV*512];
// bf16 split buffers (tensor-core GEMM operands)
__device__ __align__(256) bf16 g_fusehi[BSZ*NV*1792];
__device__ __align__(256) bf16 g_fuselo[BSZ*NV*1792];
__device__ __align__(256) bf16 g_h1hi[BSZ*NV*512];
__device__ __align__(256) bf16 g_h1lo[BSZ*NV*512];
__device__ __align__(256) bf16 g_cw1hi[512*1792];
__device__ __align__(256) bf16 g_cw1lo[512*1792];
__device__ __align__(256) bf16 g_cw2hi[512*512];
__device__ __align__(256) bf16 g_cw2lo[512*512];
__device__ __align__(256) bf16 g_fm0hi[BSZ*NV*128];
__device__ __align__(256) bf16 g_fm0lo[BSZ*NV*128];
__device__ __align__(256) bf16 g_fmp1hi[BSZ*NP1*128];
__device__ __align__(256) bf16 g_fmp1lo[BSZ*NP1*128];
__device__ __align__(256) bf16 g_fm2hi[BSZ*NP1*256];
__device__ __align__(256) bf16 g_fm2lo[BSZ*NP1*256];
__device__ __align__(256) bf16 g_fmp2hi[BSZ*NP2*256];
__device__ __align__(256) bf16 g_fmp2lo[BSZ*NP2*256];
__device__ __align__(256) bf16 g_w1thi[256*128];
__device__ __align__(256) bf16 g_w1tlo[256*128];
__device__ __align__(256) bf16 g_w2thi[512*128];
__device__ __align__(256) bf16 g_w2tlo[512*128];
__device__ __align__(256) bf16 g_w3thi[512*256];
__device__ __align__(256) bf16 g_w3tlo[512*256];
__device__ __align__(256) bf16 g_w4thi[1024*256];
__device__ __align__(256) bf16 g_w4tlo[1024*256];
// pre-normalized direction vectors
__device__ float g_dn0[3*128];
__device__ float g_dn1[3*128];
__device__ float g_dn2[3*256];
__device__ float g_dn3[3*256];
__device__ float g_dn4[3*512];

// ---------------- PTX helpers (arch-agnostic: sm_80-era instructions) --------
__device__ __forceinline__ uint32_t smem_u32(const void* p){
    uint32_t a;
    asm("{ .reg .u64 t; cvta.to.shared.u64 t, %1; cvt.u32.u64 %0, t; }" : "=r"(a) : "l"(p));
    return a;
}
#define CP_ASYNC16(dst, src) \
    asm volatile("cp.async.ca.shared.global [%0], [%1], 16;" :: "r"(dst), "l"(src) : "memory")
#define CP_COMMIT() asm volatile("cp.async.commit_group;" ::: "memory")
#define CP_WAIT(n)  asm volatile("cp.async.wait_group %0;" :: "n"(n) : "memory")
#define LDSM_X4(r, a) \
    asm volatile("ldmatrix.sync.aligned.m8n8.x4.shared.b16 {%0,%1,%2,%3}, [%4];" \
        : "=r"((r)[0]),"=r"((r)[1]),"=r"((r)[2]),"=r"((r)[3]) : "r"(a))
#define LDSM_X2(r, a) \
    asm volatile("ldmatrix.sync.aligned.m8n8.x2.shared.b16 {%0,%1}, [%2];" \
        : "=r"((r)[0]),"=r"((r)[1]) : "r"(a))
#define MMA_BF16(d, a, b) \
    asm volatile("mma.sync.aligned.m16n8k16.row.col.f32.bf16.bf16.f32 " \
        "{%0,%1,%2,%3}, {%4,%5,%6,%7}, {%8,%9}, {%0,%1,%2,%3};" \
        : "+f"((d)[0]),"+f"((d)[1]),"+f"((d)[2]),"+f"((d)[3]) \
        : "r"((a)[0]),"r"((a)[1]),"r"((a)[2]),"r"((a)[3]), "r"((b)[0]),"r"((b)[1]))

// ---------------- split fp32 -> bf16 hi/lo -----------------------------------
__global__ void split_kernel(const float* __restrict__ src,
                             bf16* __restrict__ hi, bf16* __restrict__ lo, int n)
{
    int i = blockIdx.x*256 + threadIdx.x;
    if (i < n) {
        float v = src[i];
        bf16 h = __float2bfloat16(v);
        hi[i] = h;
        lo[i] = __float2bfloat16(v - __bfloat162float(h));
    }
}

// ---------------- transpose-split: w (K,N) -> wT hi/lo (N,K) -----------------
__global__ void tsplit_kernel(const float* __restrict__ w, int K, int N,
                              bf16* __restrict__ hi, bf16* __restrict__ lo)
{
    int n = blockIdx.x;
    for (int k = threadIdx.x; k < K; k += blockDim.x) {
        float v = w[(size_t)k*N + n];
        bf16 h = __float2bfloat16(v);
        hi[(size_t)n*K + k] = h;
        lo[(size_t)n*K + k] = __float2bfloat16(v - __bfloat162float(h));
    }
}

// ---------------- normalize direction vectors (3,C) once ---------------------
__global__ void ndirs_kernel(const float* __restrict__ d, float* __restrict__ o, int C)
{
    int c = blockIdx.x*128 + threadIdx.x;
    if (c < C) {
        float x = d[c], y = d[C+c], z = d[2*C+c];
        float n = sqrtf(x*x + y*y + z*z);
        float inv = 1.0f / fmaxf(n, 1e-12f);
        o[c] = x*inv; o[C+c] = y*inv; o[2*C+c] = z*inv;
    }
}

// ================= warp-MMA GEMM v2: 512 threads, 32x32 warp tiles ===========
// C(128x128 tile) = A @ B^T + bias.  A:(M,K) hi/lo, B:(N,K) hi/lo, row-major.
// Split: D = Ah@Bh + Ah@Bl + Al@Bh (fp32 accum).  16 warps/CTA for latency hiding.
#define MMA_SMEM_TOTAL (2*65536)
template<int KTOT, bool RELU, bool OUT_SPLIT>
__global__ __launch_bounds__(512, 1)
void mma_gemm(const bf16* __restrict__ Ahi, const bf16* __restrict__ Alo,
              const bf16* __restrict__ Bhi, const bf16* __restrict__ Blo,
              const float* __restrict__ bias, int Nstride,
              float* __restrict__ Cf, bf16* __restrict__ Chi, bf16* __restrict__ Clo)
{
    extern __shared__ __align__(1024) char smem[];
    const uint32_t sbase = smem_u32(smem);
    const int tid  = threadIdx.x;
    const int lane = tid & 31, warp = tid >> 5;     // 16 warps
    const int m0 = blockIdx.y * 128, n0 = blockIdx.x * 128;
    const int wm = (warp >> 2) * 32, wn = (warp & 3) * 32;

    // loader: 512 thr; per buffer 128 rows x 128B; thread -> 2 rows per buffer
    const int      lr0  = tid >> 3;          // 0..63
    const uint32_t lc16 = (tid & 7) * 16;
    const int      lcel = (tid & 7) * 8;

    const bf16* srcs[4] = { Ahi + (size_t)m0*KTOT, Alo + (size_t)m0*KTOT,
                            Bhi + (size_t)n0*KTOT, Blo + (size_t)n0*KTOT };

    float acc[2][4][4];
#pragma unroll
    for (int mi=0;mi<2;mi++)
#pragma unroll
        for (int ni=0;ni<4;ni++)
#pragma unroll
            for (int q=0;q<4;q++) acc[mi][ni][q]=0.f;

    const int NCH = KTOT / 64;

    {
        const size_t kb = lcel;
#pragma unroll
        for (int b=0;b<4;b++)
#pragma unroll
            for (int it=0;it<2;it++) {
                const int row = lr0 + it*64;
                const uint32_t dst = sbase + b*16384u + row*128u + (lc16 ^ ((row&7)<<4));
                CP_ASYNC16(dst, (const void*)(srcs[b] + (size_t)row*KTOT + kb));
            }
        CP_COMMIT();
    }

    const int      arow_in = (lane & 7) + (lane & 8);
    const uint32_t abyte   = (lane & 16) ? 16u : 0u;
    const int      brow_in = lane & 7;
    const uint32_t bbyte   = (lane & 8) ? 16u : 0u;

    for (int i=0;i<NCH;i++) {
        if (i+1 < NCH) {
            const uint32_t sb = sbase + ((i+1)&1)*65536u;
            const size_t kb = (size_t)(i+1)*64 + lcel;
#pragma unroll
            for (int b=0;b<4;b++)
#pragma unroll
                for (int it=0;it<2;it++) {
                    const int row = lr0 + it*64;
                    const uint32_t dst = sb + b*16384u + row*128u + (lc16 ^ ((row&7)<<4));
                    CP_ASYNC16(dst, (const void*)(srcs[b] + (size_t)row*KTOT + kb));
                }
            CP_COMMIT();
            CP_WAIT(1);
        } else {
            CP_WAIT(0);
        }
        __syncthreads();

        const uint32_t sb = sbase + (i&1)*65536u;
#pragma unroll
        for (int kk=0;kk<4;kk++) {
            const uint32_t kbb = kk*32u;
            uint32_t ah[2][4], al[2][4], bhf[4][2], blf[4][2];
#pragma unroll
            for (int mi=0;mi<2;mi++) {
                const int row = wm + mi*16 + arow_in;
                const uint32_t off = row*128u + ((kbb + abyte) ^ ((row&7)<<4));
                LDSM_X4(ah[mi], sb + off);
                LDSM_X4(al[mi], sb + 16384u + off);
            }
#pragma unroll
            for (int ni=0;ni<4;ni++) {
                const int row = wn + ni*8 + brow_in;
                const uint32_t off = row*128u + ((kbb + bbyte) ^ ((row&7)<<4));
                LDSM_X2(bhf[ni], sb + 32768u + off);
                LDSM_X2(blf[ni], sb + 49152u + off);
            }
#pragma unroll
            for (int mi=0;mi<2;mi++)
#pragma unroll
                for (int ni=0;ni<4;ni++) {
                    MMA_BF16(acc[mi][ni], ah[mi], bhf[ni]);
                    MMA_BF16(acc[mi][ni], ah[mi], blf[ni]);
                    MMA_BF16(acc[mi][ni], al[mi], bhf[ni]);
                }
        }
        __syncthreads();
    }

#pragma unroll
    for (int mi=0;mi<2;mi++) {
        const int r0g = m0 + wm + mi*16 + (lane>>2);
#pragma unroll
        for (int ni=0;ni<4;ni++) {
            const int col = n0 + wn + ni*8 + (lane&3)*2;
            const float b0 = bias[col], b1 = bias[col+1];
            float v0 = acc[mi][ni][0] + b0, v1 = acc[mi][ni][1] + b1;
            float v2 = acc[mi][ni][2] + b0, v3 = acc[mi][ni][3] + b1;
            if (RELU) {
                v0 = fmaxf(v0,0.f); v1 = fmaxf(v1,0.f);
                v2 = fmaxf(v2,0.f); v3 = fmaxf(v3,0.f);
            }
            const size_t g0 = (size_t)r0g*Nstride + col;
            const size_t g1 = (size_t)(r0g+8)*Nstride + col;
            if (OUT_SPLIT) {
                bf16 h0 = __float2bfloat16(v0), h1 = __float2bfloat16(v1);
                bf16 h2b = __float2bfloat16(v2), h3 = __float2bfloat16(v3);
                Chi[g0] = h0; Chi[g0+1] = h1;
                Chi[g1] = h2b; Chi[g1+1] = h3;
                Clo[g0]   = __float2bfloat16(v0 - __bfloat162float(h0));
                Clo[g0+1] = __float2bfloat16(v1 - __bfloat162float(h1));
                Clo[g1]   = __float2bfloat16(v2 - __bfloat162float(h2b));
                Clo[g1+1] = __float2bfloat16(v3 - __bfloat162float(h3));
            } else {
                float2 p0 = make_float2(v0, v1), p1 = make_float2(v2, v3);
                *(float2*)&Cf[g0] = p0;
                *(float2*)&Cf[g1] = p1;
            }
        }
    }
}

// ---------------- KNN: brute force, branch-free register top-K ---------------
template<int K>
__global__ void knn_kernel(const float* __restrict__ verts,
                           const int* __restrict__ qidx, // null => identity
                           int nq, int V, int* __restrict__ out)
{
    int b = blockIdx.y;
    int q = blockIdx.x * 128 + threadIdx.x;
    const float* vb = verts + (size_t)b * V * 3;
    bool active = q < nq;
    int self = -1;
    float qx=0.f, qy=0.f, qz=0.f, qa2=0.f;
    if (active) {
        self = qidx ? qidx[q] : q;
        qx = vb[self*3+0]; qy = vb[self*3+1]; qz = vb[self*3+2];
        qa2 = qx*qx + qy*qy + qz*qz;
    }
    float dk[K]; int ik[K];
#pragma unroll
    for (int i=0;i<K;i++){ dk[i]=3.4e38f; ik[i]=0; }
    float worst = 3.4e38f;
    int   wpos  = 0;

    __shared__ float4 sp[128];
    for (int t0=0; t0<V; t0+=128) {
        int j = t0 + threadIdx.x;
        float x = vb[j*3+0], y = vb[j*3+1], z = vb[j*3+2];
        sp[threadIdx.x] = make_float4(x,y,z, x*x+y*y+z*z);
        __syncthreads();
        if (active) {
#pragma unroll 4
            for (int jj=0; jj<128; jj++) {
                float4 p = sp[jj];
                float d = qa2 + p.w - 2.0f*(qx*p.x + qy*p.y + qz*p.z);
                int gj = t0 + jj;
                if (d < worst && gj != self) {
                    float w = -3.4e38f; int wp = 0;
#pragma unroll
                    for (int i=0;i<K;i++) {
                        if (i == wpos) { dk[i] = d; ik[i] = gj; }
                        if (dk[i] > w) { w = dk[i]; wp = i; }
                    }
                    worst = w; wpos = wp;
                }
            }
        }
        __syncthreads();
    }
    if (active) {
        int* o = out + ((size_t)b*nq + q)*K;
#pragma unroll
        for (int i=0;i<K;i++) o[i]=ik[i];
    }
}

// ---------------- conv_surface (fm0) ----------------------------------------
__global__ void conv_surface_kernel(const float* __restrict__ verts,
                                    const int* __restrict__ nb,
                                    const float* __restrict__ dn0,
                                    float* __restrict__ fm0)
{
    int bv = blockIdx.x;
    int b = bv >> 12, v = bv & (NV-1);
    const float* vb = verts + (size_t)b*NV*3;
    __shared__ float sdx[KNN], sdy[KNN], sdz[KNN];
    int t = threadIdx.x;
    float cx = vb[v*3+0], cy = vb[v*3+1], cz = vb[v*3+2];
    if (t < KNN) {
        int j = nb[(size_t)bv*KNN + t];
        float dx = vb[j*3+0]-cx, dy = vb[j*3+1]-cy, dz = vb[j*3+2]-cz;
        float n = sqrtf(dx*dx+dy*dy+dz*dz);
        float inv = 1.0f / fmaxf(n, 1e-12f);
        sdx[t]=dx*inv; sdy[t]=dy*inv; sdz[t]=dz*inv;
    }
    __syncthreads();
    int k = t;
    float d0 = dn0[k], d1 = dn0[128+k], d2 = dn0[256+k];
    float m = 0.0f;
#pragma unroll
    for (int j=0;j<KNN;j++)
        m = fmaxf(m, sdx[j]*d0 + sdy[j]*d1 + sdz[j]*d2);
    fm0[(size_t)bv*128 + k] = m;
}

// ---------------- conv_layer epilogue (dirs prenormalized) -------------------
template<int COUT, bool RELU>
__global__ void conv_layer_kernel(const float* __restrict__ verts, int V,
                                  const int* __restrict__ nb,
                                  const float* __restrict__ f,
                                  const float* __restrict__ dn,
                                  float* __restrict__ out)
{
    int bv = blockIdx.x;
    int b = bv / V, v = bv - b*V;
    const float* vb = verts + (size_t)b*V*3;
    __shared__ float sdx[KNN], sdy[KNN], sdz[KNN];
    __shared__ int   si[KNN];
    int t = threadIdx.x;
    float cx = vb[v*3+0], cy = vb[v*3+1], cz = vb[v*3+2];
    if (t < KNN) {
        int j = nb[(size_t)bv*KNN + t];
        si[t] = j;
        float dx = vb[j*3+0]-cx, dy = vb[j*3+1]-cy, dz = vb[j*3+2]-cz;
        float n = sqrtf(dx*dx+dy*dy+dz*dz);
        float inv = 1.0f / fmaxf(n, 1e-12f);
        sdx[t]=dx*inv; sdy[t]=dy*inv; sdz[t]=dz*inv;
    }
    __syncthreads();
    const float* fb = f + (size_t)b*V*(2*COUT);
    for (int co = t; co < COUT; co += blockDim.x) {
        float d0 = dn[co], d1 = dn[COUT+co], d2 = dn[2*COUT+co];
        float m = -3.4e38f;
#pragma unroll 8
        for (int j=0;j<KNN;j++) {
            float th = fmaxf(sdx[j]*d0 + sdy[j]*d1 + sdz[j]*d2, 0.0f);
            float val = th * fb[si[j]*(2*COUT) + COUT + co];
            m = fmaxf(m, val);
        }
        float r = fb[v*(2*COUT) + co] + m;
        out[((size_t)b*V+v)*COUT + co] = RELU ? fmaxf(r, 0.0f) : r;
    }
}

// ---------------- pool ------------------------------------------------------
__global__ void pool_kernel(const float* __restrict__ verts,
                            const float* __restrict__ fm,
                            int V, int C,
                            const int* __restrict__ sidx,
                            const int* __restrict__ nb4, int ns,
                            float* __restrict__ vout, float* __restrict__ fout)
{
    int bq = blockIdx.x;
    int b = bq / ns, q = bq - b*ns;
    int t = threadIdx.x;
    int sv = sidx[q];
    if (t < 3) vout[(size_t)bq*3 + t] = verts[((size_t)b*V + sv)*3 + t];
    const int* nbq = nb4 + (size_t)bq*4;
    int j0=nbq[0], j1=nbq[1], j2=nbq[2], j3=nbq[3];
    const float* fb = fm + (size_t)b*V*C;
    for (int c=t; c<C; c+=blockDim.x) {
        float m = fmaxf(fmaxf(fb[j0*C+c], fb[j1*C+c]),
                        fmaxf(fb[j2*C+c], fb[j3*C+c]));
        fout[(size_t)bq*C + c] = m;
    }
}

// ---------------- nearest ---------------------------------------------------
__global__ void nearest_kernel(const float* __restrict__ verts,
                               const float* __restrict__ src,
                               int V, int S, int* __restrict__ out)
{
    int b = blockIdx.y;
    int q = blockIdx.x * 128 + threadIdx.x;
    const float* vb = verts + (size_t)b*V*3;
    const float* sb = src + (size_t)b*S*3;
    float qx = vb[q*3+0], qy = vb[q*3+1], qz = vb[q*3+2];
    float qa2 = qx*qx + qy*qy + qz*qz;
    float best = 3.4e38f; int bi = 0;
    __shared__ float4 sp[128];
    for (int t0=0; t0<S; t0+=128) {
        int j = t0 + threadIdx.x;
        float x = sb[j*3+0], y = sb[j*3+1], z = sb[j*3+2];
        sp[threadIdx.x] = make_float4(x,y,z, x*x+y*y+z*z);
        __syncthreads();
        for (int jj=0; jj<128; jj++) {
            float4 p = sp[jj];
            float d = qa2 + p.w - 2.0f*(qx*p.x + qy*p.y + qz*p.z);
            if (d < best) { best = d; bi = t0+jj; }
        }
        __syncthreads();
    }
    out[(size_t)b*V + q] = bi;
}

// ---------------- global feature --------------------------------------------
__global__ void fglobal_kernel(const float* __restrict__ fm4, float* __restrict__ g)
{
    int b = blockIdx.x, c = threadIdx.x;
    float m = -3.4e38f;
    for (int v=0; v<NP2; v++) m = fmaxf(m, fm4[((size_t)b*NP2+v)*512 + c]);
    g[(size_t)b*512 + c] = m;
}

// ---------------- fuse assembly -> bf16 hi/lo ---------------------------------
__global__ void fuse_kernel(const float* __restrict__ fm0, const float* __restrict__ fm1,
                            const float* __restrict__ fm2, const float* __restrict__ fm3,
                            const float* __restrict__ fm4, const float* __restrict__ fg,
                            const int* __restrict__ near1, const int* __restrict__ near2,
                            bf16* __restrict__ fhi, bf16* __restrict__ flo)
{
    int bv = blockIdx.x;
    int b = bv >> 12;
    int n1 = near1[bv], n2 = near2[bv];
    size_t o = (size_t)bv*1792;
    for (int c = threadIdx.x; c < 1792; c += blockDim.x) {
        float val;
        if (c < 128)        val = fm0[(size_t)bv*128 + c];
        else if (c < 256)   val = fm1[(size_t)bv*128 + (c-128)];
        else if (c < 512)   val = fm2[((size_t)b*NP1+n1)*256 + (c-256)];
        else if (c < 768)   val = fm3[((size_t)b*NP1+n1)*256 + (c-512)];
        else if (c < 1280)  val = fm4[((size_t)b*NP2+n2)*512 + (c-768)];
        else                val = fg [(size_t)b*512 + (c-1280)];
        bf16 h = __float2bfloat16(val);
        fhi[o+c] = h;
        flo[o+c] = __float2bfloat16(val - __bfloat162float(h));
    }
}

// ---------------- head: out(16 rows x 13) = h2 @ cw3^T + cb3 ----------------
__global__ void head_kernel(const float* __restrict__ h2,
                            const float* __restrict__ cw3,
                            const float* __restrict__ cb3,
                            float* __restrict__ out)
{
    __shared__ float sh[16][512];
    __shared__ float sw[13*513];
    const int tid = threadIdx.x;
    const int r = tid >> 4, c = tid & 15;
    const int row0 = blockIdx.x * 16;
    for (int i = tid; i < 16*512; i += 256)
        sh[i>>9][i&511] = h2[(size_t)row0*512 + i];
    for (int i = tid; i < 13*512; i += 256)
        sw[(i>>9)*513 + (i&511)] = cw3[i];
    __syncthreads();
    if (c < 13) {
        float acc = cb3[c];
        const float* w = &sw[c*513];
        const float* hrow = sh[r];
#pragma unroll 8
        for (int k=0;k<512;k++) acc += hrow[k]*w[k];
        out[(size_t)(row0+r)*13 + c] = acc;
    }
}

// -----------------------------------------------------------------------------
static void* sym_addr(const void* symbol) {
    void* p = nullptr;
    cudaGetSymbolAddress(&p, symbol);
    return p;
}

extern "C" void kernel_launch(void* const* d_in, const int* in_sizes, int n_in,
                              void* d_out, int out_size)
{
    (void)in_sizes; (void)n_in; (void)out_size;
    const float* vertices = (const float*)d_in[0];
    const int*   sidx1    = (const int*)  d_in[1];
    const int*   sidx2    = (const int*)  d_in[2];
    const float* dir0     = (const float*)d_in[3];
    const float* w1 = (const float*)d_in[4];  const float* b1 = (const float*)d_in[5];  const float* d1 = (const float*)d_in[6];
    const float* w2 = (const float*)d_in[7];  const float* b2 = (const float*)d_in[8];  const float* d2 = (const float*)d_in[9];
    const float* w3 = (const float*)d_in[10]; const float* b3 = (const float*)d_in[11]; const float* d3 = (const float*)d_in[12];
    const float* w4 = (const float*)d_in[13]; const float* b4 = (const float*)d_in[14]; const float* d4 = (const float*)d_in[15];
    const float* cw1 = (const float*)d_in[16]; const float* cb1 = (const float*)d_in[17];
    const float* cw2 = (const float*)d_in[18]; const float* cb2 = (const float*)d_in[19];
    const float* cw3 = (const float*)d_in[20]; const float* cb3 = (const float*)d_in[21];
    float* out = (float*)d_out;

    int*   nb1   = (int*)  sym_addr(g_nb1);
    int*   nb2   = (int*)  sym_addr(g_nb2);
    int*   nb3   = (int*)  sym_addr(g_nb3);
    int*   nbp   = (int*)  sym_addr(g_nbp);
    int*   near1 = (int*)  sym_addr(g_near1);
    int*   near2 = (int*)  sym_addr(g_near2);
    float* fm0   = (float*)sym_addr(g_fm0);
    float* fm1   = (float*)sym_addr(g_fm1);
    float* fbuf  = (float*)sym_addr(g_f);
    float* vp1   = (float*)sym_addr(g_vp1);
    float* fmp1  = (float*)sym_addr(g_fmp1);
    float* fm2   = (float*)sym_addr(g_fm2);
    float* fm3   = (float*)sym_addr(g_fm3);
    float* vp2   = (float*)sym_addr(g_vp2);
    float* fmp2  = (float*)sym_addr(g_fmp2);
    float* fm4   = (float*)sym_addr(g_fm4);
    float* fglob = (float*)sym_addr(g_fglob);
    float* h2    = (float*)sym_addr(g_h2);
    bf16* fusehi = (bf16*)sym_addr(g_fusehi);
    bf16* fuselo = (bf16*)sym_addr(g_fuselo);
    bf16* h1hi   = (bf16*)sym_addr(g_h1hi);
    bf16* h1lo   = (bf16*)sym_addr(g_h1lo);
    bf16* cw1hi  = (bf16*)sym_addr(g_cw1hi);
    bf16* cw1lo  = (bf16*)sym_addr(g_cw1lo);
    bf16* cw2hi  = (bf16*)sym_addr(g_cw2hi);
    bf16* cw2lo  = (bf16*)sym_addr(g_cw2lo);
    bf16* fm0hi  = (bf16*)sym_addr(g_fm0hi);   bf16* fm0lo  = (bf16*)sym_addr(g_fm0lo);
    bf16* fmp1hi = (bf16*)sym_addr(g_fmp1hi);  bf16* fmp1lo = (bf16*)sym_addr(g_fmp1lo);
    bf16* fm2hi  = (bf16*)sym_addr(g_fm2hi);   bf16* fm2lo  = (bf16*)sym_addr(g_fm2lo);
    bf16* fmp2hi = (bf16*)sym_addr(g_fmp2hi);  bf16* fmp2lo = (bf16*)sym_addr(g_fmp2lo);
    bf16* w1thi  = (bf16*)sym_addr(g_w1thi);   bf16* w1tlo  = (bf16*)sym_addr(g_w1tlo);
    bf16* w2thi  = (bf16*)sym_addr(g_w2thi);   bf16* w2tlo  = (bf16*)sym_addr(g_w2tlo);
    bf16* w3thi  = (bf16*)sym_addr(g_w3thi);   bf16* w3tlo  = (bf16*)sym_addr(g_w3tlo);
    bf16* w4thi  = (bf16*)sym_addr(g_w4thi);   bf16* w4tlo  = (bf16*)sym_addr(g_w4tlo);
    float* dn0 = (float*)sym_addr(g_dn0);
    float* dn1 = (float*)sym_addr(g_dn1);
    float* dn2 = (float*)sym_addr(g_dn2);
    float* dn3 = (float*)sym_addr(g_dn3);
    float* dn4 = (float*)sym_addr(g_dn4);

    cudaFuncSetAttribute(mma_gemm<1792,true,true>,  cudaFuncAttributeMaxDynamicSharedMemorySize, MMA_SMEM_TOTAL);
    cudaFuncSetAttribute(mma_gemm<512,true,false>,  cudaFuncAttributeMaxDynamicSharedMemorySize, MMA_SMEM_TOTAL);
    cudaFuncSetAttribute(mma_gemm<128,false,false>, cudaFuncAttributeMaxDynamicSharedMemorySize, MMA_SMEM_TOTAL);
    cudaFuncSetAttribute(mma_gemm<256,false,false>, cudaFuncAttributeMaxDynamicSharedMemorySize, MMA_SMEM_TOTAL);

    // idx0-2: weight splits + one ndirs, so knn lands at PROFILED index 3
    split_kernel<<<(512*1792+255)/256, 256>>>(cw1, cw1hi, cw1lo, 512*1792);
    split_kernel<<<(512*512+255)/256, 256>>>(cw2, cw2hi, cw2lo, 512*512);
    ndirs_kernel<<<1, 128>>>(dir0, dn0, 128);
    // idx3: full-res KNN(32)  <-- ncu capture target
    knn_kernel<KNN><<<dim3(NV/128, BSZ), 128>>>(vertices, nullptr, NV, NV, nb1);
    // remaining prep (tiny)
    ndirs_kernel<<<1, 128>>>(d1, dn1, 128);
    ndirs_kernel<<<2, 128>>>(d2, dn2, 256);
    ndirs_kernel<<<2, 128>>>(d3, dn3, 256);
    ndirs_kernel<<<4, 128>>>(d4, dn4, 512);
    tsplit_kernel<<<256, 128>>>(w1, 128, 256, w1thi, w1tlo);
    tsplit_kernel<<<512, 128>>>(w2, 128, 512, w2thi, w2tlo);
    tsplit_kernel<<<512, 256>>>(w3, 256, 512, w3thi, w3tlo);
    tsplit_kernel<<<1024, 256>>>(w4, 256, 1024, w4thi, w4tlo);
    // fm0 = conv_surface
    conv_surface_kernel<<<BSZ*NV, 128>>>(vertices, nb1, dn0, fm0);
    split_kernel<<<(BSZ*NV*128+255)/256, 256>>>(fm0, fm0hi, fm0lo, BSZ*NV*128);
    // fm1 = relu(conv_layer(fm0; w1,b1,d1; 128))
    mma_gemm<128,false,false><<<dim3(2, (BSZ*NV)/128), 512, MMA_SMEM_TOTAL>>>(
        fm0hi, fm0lo, w1thi, w1tlo, b1, 256, fbuf, nullptr, nullptr);
    conv_layer_kernel<128,true><<<BSZ*NV, 128>>>(vertices, NV, nb1, fbuf, dn1, fm1);
    // pool1
    knn_kernel<4><<<dim3(NP1/128, BSZ), 128>>>(vertices, sidx1, NP1, NV, nbp);
    pool_kernel<<<BSZ*NP1, 128>>>(vertices, fm1, NV, 128, sidx1, nbp, NP1, vp1, fmp1);
    split_kernel<<<(BSZ*NP1*128+255)/256, 256>>>(fmp1, fmp1hi, fmp1lo, BSZ*NP1*128);
    // KNN level 1
    knn_kernel<KNN><<<dim3(NP1/128, BSZ), 128>>>(vp1, nullptr, NP1, NP1, nb2);
    // fm2
    mma_gemm<128,false,false><<<dim3(4, (BSZ*NP1)/128), 512, MMA_SMEM_TOTAL>>>(
        fmp1hi, fmp1lo, w2thi, w2tlo, b2, 512, fbuf, nullptr, nullptr);
    conv_layer_kernel<256,true><<<BSZ*NP1, 256>>>(vp1, NP1, nb2, fbuf, dn2, fm2);
    split_kernel<<<(BSZ*NP1*256+255)/256, 256>>>(fm2, fm2hi, fm2lo, BSZ*NP1*256);
    // fm3
    mma_gemm<256,false,false><<<dim3(4, (BSZ*NP1)/128), 512, MMA_SMEM_TOTAL>>>(
        fm2hi, fm2lo, w3thi, w3tlo, b3, 512, fbuf, nullptr, nullptr);
    conv_layer_kernel<256,true><<<BSZ*NP1, 256>>>(vp1, NP1, nb2, fbuf, dn3, fm3);
    // pool2
    knn_kernel<4><<<dim3(NP2/128, BSZ), 128>>>(vp1, sidx2, NP2, NP1, nbp);
    pool_kernel<<<BSZ*NP2, 256>>>(vp1, fm3, NP1, 256, sidx2, nbp, NP2, vp2, fmp2);
    split_kernel<<<(BSZ*NP2*256+255)/256, 256>>>(fmp2, fmp2hi, fmp2lo, BSZ*NP2*256);
    // KNN level 2
    knn_kernel<KNN><<<dim3(NP2/128, BSZ), 128>>>(vp2, nullptr, NP2, NP2, nb3);
    // fm4
    mma_gemm<256,false,false><<<dim3(8, (BSZ*NP2)/128), 512, MMA_SMEM_TOTAL>>>(
        fmp2hi, fmp2lo, w4thi, w4tlo, b4, 1024, fbuf, nullptr, nullptr);
    conv_layer_kernel<512,false><<<BSZ*NP2, 256>>>(vp2, NP2, nb3, fbuf, dn4, fm4);
    // global max feature
    fglobal_kernel<<<BSZ, 512>>>(fm4, fglob);
    // nearest upsample indices
    nearest_kernel<<<dim3(NV/128, BSZ), 128>>>(vertices, vp1, NV, NP1, near1);
    nearest_kernel<<<dim3(NV/128, BSZ), 128>>>(vertices, vp2, NV, NP2, near2);
    // fuse -> bf16 hi/lo
    fuse_kernel<<<BSZ*NV, 256>>>(fm0, fm1, fm2, fm3, fm4, fglob, near1, near2, fusehi, fuselo);
    // h1 = relu(fuse @ cw1^T + cb1)
    mma_gemm<1792,true,true><<<dim3(4, (BSZ*NV)/128), 512, MMA_SMEM_TOTAL>>>(
        fusehi, fuselo, cw1hi, cw1lo, cb1, 512, nullptr, h1hi, h1lo);
    // h2 = relu(h1 @ cw2^T + cb2)
    mma_gemm<512,true,false><<<dim3(4, (BSZ*NV)/128), 512, MMA_SMEM_TOTAL>>>(
        h1hi, h1lo, cw2hi, cw2lo, cb2, 512, h2, nullptr, nullptr);
    // logits
    head_kernel<<<(BSZ*NV)/16, 256>>>(h2, cw3, cb3, out);
}

// round 9
// speedup vs baseline: 1.4501x; 1.4201x over previous
#include <cuda_runtime.h>
#include <cuda_bf16.h>
#include <math.h>
#include <stdint.h>

#define BSZ 4
#define NV  4096
#define NP1 1024
#define NP2 256
#define KNN 32
typedef __nv_bfloat16 bf16;

// ---------------- scratch (device globals; no allocation allowed) ------------
__device__ int   g_nb1[BSZ*NV*KNN];
__device__ int   g_nb2[BSZ*NP1*KNN];
__device__ int   g_nb3[BSZ*NP2*KNN];
__device__ int   g_nbp[BSZ*NP1*4];
__device__ int   g_near1[BSZ*NV];
__device__ int   g_near2[BSZ*NV];
__device__ float g_fm0[BSZ*NV*128];
__device__ float g_fm1[BSZ*NV*128];
__device__ float g_f  [BSZ*NV*256];
__device__ float g_vp1[BSZ*NP1*3];
__device__ float g_fmp1[BSZ*NP1*128];
__device__ float g_fm2[BSZ*NP1*256];
__device__ float g_fm3[BSZ*NP1*256];
__device__ float g_vp2[BSZ*NP2*3];
__device__ float g_fmp2[BSZ*NP2*256];
__device__ float g_fm4[BSZ*NP2*512];
__device__ float g_fglob[BSZ*512];
__device__ float g_h2[BSZ*NV*512];
// bf16 split buffers (tensor-core GEMM operands)
__device__ __align__(256) bf16 g_fusehi[BSZ*NV*1792];
__device__ __align__(256) bf16 g_fuselo[BSZ*NV*1792];
__device__ __align__(256) bf16 g_h1hi[BSZ*NV*512];
__device__ __align__(256) bf16 g_h1lo[BSZ*NV*512];
__device__ __align__(256) bf16 g_cw1hi[512*1792];
__device__ __align__(256) bf16 g_cw1lo[512*1792];
__device__ __align__(256) bf16 g_cw2hi[512*512];
__device__ __align__(256) bf16 g_cw2lo[512*512];
__device__ __align__(256) bf16 g_fm0hi[BSZ*NV*128];
__device__ __align__(256) bf16 g_fm0lo[BSZ*NV*128];
__device__ __align__(256) bf16 g_fmp1hi[BSZ*NP1*128];
__device__ __align__(256) bf16 g_fmp1lo[BSZ*NP1*128];
__device__ __align__(256) bf16 g_fm2hi[BSZ*NP1*256];
__device__ __align__(256) bf16 g_fm2lo[BSZ*NP1*256];
__device__ __align__(256) bf16 g_fmp2hi[BSZ*NP2*256];
__device__ __align__(256) bf16 g_fmp2lo[BSZ*NP2*256];
__device__ __align__(256) bf16 g_w1thi[256*128];
__device__ __align__(256) bf16 g_w1tlo[256*128];
__device__ __align__(256) bf16 g_w2thi[512*128];
__device__ __align__(256) bf16 g_w2tlo[512*128];
__device__ __align__(256) bf16 g_w3thi[512*256];
__device__ __align__(256) bf16 g_w3tlo[512*256];
__device__ __align__(256) bf16 g_w4thi[1024*256];
__device__ __align__(256) bf16 g_w4tlo[1024*256];
// pre-normalized direction vectors
__device__ float g_dn0[3*128];
__device__ float g_dn1[3*128];
__device__ float g_dn2[3*256];
__device__ float g_dn3[3*256];
__device__ float g_dn4[3*512];

// ---------------- PTX helpers (arch-agnostic: sm_80-era instructions) --------
__device__ __forceinline__ uint32_t smem_u32(const void* p){
    uint32_t a;
    asm("{ .reg .u64 t; cvta.to.shared.u64 t, %1; cvt.u32.u64 %0, t; }" : "=r"(a) : "l"(p));
    return a;
}
#define CP_ASYNC16(dst, src) \
    asm volatile("cp.async.ca.shared.global [%0], [%1], 16;" :: "r"(dst), "l"(src) : "memory")
#define CP_COMMIT() asm volatile("cp.async.commit_group;" ::: "memory")
#define CP_WAIT(n)  asm volatile("cp.async.wait_group %0;" :: "n"(n) : "memory")
#define LDSM_X4(r, a) \
    asm volatile("ldmatrix.sync.aligned.m8n8.x4.shared.b16 {%0,%1,%2,%3}, [%4];" \
        : "=r"((r)[0]),"=r"((r)[1]),"=r"((r)[2]),"=r"((r)[3]) : "r"(a))
#define LDSM_X2(r, a) \
    asm volatile("ldmatrix.sync.aligned.m8n8.x2.shared.b16 {%0,%1}, [%2];" \
        : "=r"((r)[0]),"=r"((r)[1]) : "r"(a))
#define MMA_BF16(d, a, b) \
    asm volatile("mma.sync.aligned.m16n8k16.row.col.f32.bf16.bf16.f32 " \
        "{%0,%1,%2,%3}, {%4,%5,%6,%7}, {%8,%9}, {%0,%1,%2,%3};" \
        : "+f"((d)[0]),"+f"((d)[1]),"+f"((d)[2]),"+f"((d)[3]) \
        : "r"((a)[0]),"r"((a)[1]),"r"((a)[2]),"r"((a)[3]), "r"((b)[0]),"r"((b)[1]))

// ---------------- split fp32 -> bf16 hi/lo -----------------------------------
__global__ void split_kernel(const float* __restrict__ src,
                             bf16* __restrict__ hi, bf16* __restrict__ lo, int n)
{
    int i = blockIdx.x*256 + threadIdx.x;
    if (i < n) {
        float v = src[i];
        bf16 h = __float2bfloat16(v);
        hi[i] = h;
        lo[i] = __float2bfloat16(v - __bfloat162float(h));
    }
}

// ---------------- transpose-split: w (K,N) -> wT hi/lo (N,K) -----------------
__global__ void tsplit_kernel(const float* __restrict__ w, int K, int N,
                              bf16* __restrict__ hi, bf16* __restrict__ lo)
{
    int n = blockIdx.x;
    for (int k = threadIdx.x; k < K; k += blockDim.x) {
        float v = w[(size_t)k*N + n];
        bf16 h = __float2bfloat16(v);
        hi[(size_t)n*K + k] = h;
        lo[(size_t)n*K + k] = __float2bfloat16(v - __bfloat162float(h));
    }
}

// ---------------- normalize direction vectors (3,C) once ---------------------
__global__ void ndirs_kernel(const float* __restrict__ d, float* __restrict__ o, int C)
{
    int c = blockIdx.x*128 + threadIdx.x;
    if (c < C) {
        float x = d[c], y = d[C+c], z = d[2*C+c];
        float n = sqrtf(x*x + y*y + z*z);
        float inv = 1.0f / fmaxf(n, 1e-12f);
        o[c] = x*inv; o[C+c] = y*inv; o[2*C+c] = z*inv;
    }
}

// ================= warp-MMA GEMM v2: 512 threads, 32x32 warp tiles ===========
#define MMA_SMEM_TOTAL (2*65536)
template<int KTOT, bool RELU, bool OUT_SPLIT>
__global__ __launch_bounds__(512, 1)
void mma_gemm(const bf16* __restrict__ Ahi, const bf16* __restrict__ Alo,
              const bf16* __restrict__ Bhi, const bf16* __restrict__ Blo,
              const float* __restrict__ bias, int Nstride,
              float* __restrict__ Cf, bf16* __restrict__ Chi, bf16* __restrict__ Clo)
{
    extern __shared__ __align__(1024) char smem[];
    const uint32_t sbase = smem_u32(smem);
    const int tid  = threadIdx.x;
    const int lane = tid & 31, warp = tid >> 5;     // 16 warps
    const int m0 = blockIdx.y * 128, n0 = blockIdx.x * 128;
    const int wm = (warp >> 2) * 32, wn = (warp & 3) * 32;

    const int      lr0  = tid >> 3;          // 0..63
    const uint32_t lc16 = (tid & 7) * 16;
    const int      lcel = (tid & 7) * 8;

    const bf16* srcs[4] = { Ahi + (size_t)m0*KTOT, Alo + (size_t)m0*KTOT,
                            Bhi + (size_t)n0*KTOT, Blo + (size_t)n0*KTOT };

    float acc[2][4][4];
#pragma unroll
    for (int mi=0;mi<2;mi++)
#pragma unroll
        for (int ni=0;ni<4;ni++)
#pragma unroll
            for (int q=0;q<4;q++) acc[mi][ni][q]=0.f;

    const int NCH = KTOT / 64;

    {
        const size_t kb = lcel;
#pragma unroll
        for (int b=0;b<4;b++)
#pragma unroll
            for (int it=0;it<2;it++) {
                const int row = lr0 + it*64;
                const uint32_t dst = sbase + b*16384u + row*128u + (lc16 ^ ((row&7)<<4));
                CP_ASYNC16(dst, (const void*)(srcs[b] + (size_t)row*KTOT + kb));
            }
        CP_COMMIT();
    }

    const int      arow_in = (lane & 7) + (lane & 8);
    const uint32_t abyte   = (lane & 16) ? 16u : 0u;
    const int      brow_in = lane & 7;
    const uint32_t bbyte   = (lane & 8) ? 16u : 0u;

    for (int i=0;i<NCH;i++) {
        if (i+1 < NCH) {
            const uint32_t sb = sbase + ((i+1)&1)*65536u;
            const size_t kb = (size_t)(i+1)*64 + lcel;
#pragma unroll
            for (int b=0;b<4;b++)
#pragma unroll
                for (int it=0;it<2;it++) {
                    const int row = lr0 + it*64;
                    const uint32_t dst = sb + b*16384u + row*128u + (lc16 ^ ((row&7)<<4));
                    CP_ASYNC16(dst, (const void*)(srcs[b] + (size_t)row*KTOT + kb));
                }
            CP_COMMIT();
            CP_WAIT(1);
        } else {
            CP_WAIT(0);
        }
        __syncthreads();

        const uint32_t sb = sbase + (i&1)*65536u;
#pragma unroll
        for (int kk=0;kk<4;kk++) {
            const uint32_t kbb = kk*32u;
            uint32_t ah[2][4], al[2][4], bhf[4][2], blf[4][2];
#pragma unroll
            for (int mi=0;mi<2;mi++) {
                const int row = wm + mi*16 + arow_in;
                const uint32_t off = row*128u + ((kbb + abyte) ^ ((row&7)<<4));
                LDSM_X4(ah[mi], sb + off);
                LDSM_X4(al[mi], sb + 16384u + off);
            }
#pragma unroll
            for (int ni=0;ni<4;ni++) {
                const int row = wn + ni*8 + brow_in;
                const uint32_t off = row*128u + ((kbb + bbyte) ^ ((row&7)<<4));
                LDSM_X2(bhf[ni], sb + 32768u + off);
                LDSM_X2(blf[ni], sb + 49152u + off);
            }
#pragma unroll
            for (int mi=0;mi<2;mi++)
#pragma unroll
                for (int ni=0;ni<4;ni++) {
                    MMA_BF16(acc[mi][ni], ah[mi], bhf[ni]);
                    MMA_BF16(acc[mi][ni], ah[mi], blf[ni]);
                    MMA_BF16(acc[mi][ni], al[mi], bhf[ni]);
                }
        }
        __syncthreads();
    }

#pragma unroll
    for (int mi=0;mi<2;mi++) {
        const int r0g = m0 + wm + mi*16 + (lane>>2);
#pragma unroll
        for (int ni=0;ni<4;ni++) {
            const int col = n0 + wn + ni*8 + (lane&3)*2;
            const float b0 = bias[col], b1 = bias[col+1];
            float v0 = acc[mi][ni][0] + b0, v1 = acc[mi][ni][1] + b1;
            float v2 = acc[mi][ni][2] + b0, v3 = acc[mi][ni][3] + b1;
            if (RELU) {
                v0 = fmaxf(v0,0.f); v1 = fmaxf(v1,0.f);
                v2 = fmaxf(v2,0.f); v3 = fmaxf(v3,0.f);
            }
            const size_t g0 = (size_t)r0g*Nstride + col;
            const size_t g1 = (size_t)(r0g+8)*Nstride + col;
            if (OUT_SPLIT) {
                bf16 h0 = __float2bfloat16(v0), h1 = __float2bfloat16(v1);
                bf16 h2b = __float2bfloat16(v2), h3 = __float2bfloat16(v3);
                Chi[g0] = h0; Chi[g0+1] = h1;
                Chi[g1] = h2b; Chi[g1+1] = h3;
                Clo[g0]   = __float2bfloat16(v0 - __bfloat162float(h0));
                Clo[g0+1] = __float2bfloat16(v1 - __bfloat162float(h1));
                Clo[g1]   = __float2bfloat16(v2 - __bfloat162float(h2b));
                Clo[g1+1] = __float2bfloat16(v3 - __bfloat162float(h3));
            } else {
                float2 p0 = make_float2(v0, v1), p1 = make_float2(v2, v3);
                *(float2*)&Cf[g0] = p0;
                *(float2*)&Cf[g1] = p1;
            }
        }
    }
}

// ---------------- KNN: warp-per-query, lane-distributed top-32 buffer --------
// Each lane owns ONE slot; worst/wlane warp-uniform. Candidates processed in
// ascending index order with strict d<worst gate => kept SET identical to the
// sequential insertion version. For KOUT<32: extract KOUT smallest at the end
// (top-KOUT of top-32 == global top-KOUT).
template<int KOUT>
__global__ void knn_warp(const float* __restrict__ verts,
                         const int* __restrict__ qidx, // null => identity
                         int nq, int V, int* __restrict__ out)
{
    const int b = blockIdx.y;
    const int lane = threadIdx.x & 31;
    const int warp = threadIdx.x >> 5;                // 8 warps/block
    const int q = blockIdx.x * 8 + warp;
    const float* vb = verts + (size_t)b * V * 3;
    const int self = qidx ? qidx[q] : q;
    const float qx = vb[self*3+0], qy = vb[self*3+1], qz = vb[self*3+2];
    const float qa2 = qx*qx + qy*qy + qz*qz;

    float slot_d = 3.4e38f; int slot_i = 0;
    float worst  = 3.4e38f; int wlane = 31;

    __shared__ float4 sp[128];
    for (int t0 = 0; t0 < V; t0 += 128) {
        if (threadIdx.x < 128) {
            int j = t0 + threadIdx.x;                 // V multiple of 128
            float x = vb[j*3+0], y = vb[j*3+1], z = vb[j*3+2];
            sp[threadIdx.x] = make_float4(x, y, z, x*x+y*y+z*z);
        }
        __syncthreads();
#pragma unroll
        for (int jj0 = 0; jj0 < 128; jj0 += 32) {
            float4 p = sp[jj0 + lane];
            float d = qa2 + p.w - 2.0f*(qx*p.x + qy*p.y + qz*p.z);
            int gj = t0 + jj0 + lane;
            bool pass = (d < worst) && (gj != self);
            unsigned m = __ballot_sync(0xffffffffu, pass);
            while (m) {
                int src = __ffs(m) - 1; m &= m - 1;
                float dc = __shfl_sync(0xffffffffu, d, src);
                if (dc < worst) {                     // uniform branch
                    if (lane == wlane) { slot_d = dc; slot_i = t0 + jj0 + src; }
                    float wd = slot_d; int wl = lane;
#pragma unroll
                    for (int off = 16; off; off >>= 1) {
                        float od = __shfl_xor_sync(0xffffffffu, wd, off);
                        int   ol = __shfl_xor_sync(0xffffffffu, wl, off);
                        if (od > wd || (od == wd && ol > wl)) { wd = od; wl = ol; }
                    }
                    worst = wd; wlane = wl;
                }
            }
        }
        __syncthreads();
    }
    if (KOUT == 32) {
        out[((size_t)b*nq + q)*32 + lane] = slot_i;
    } else {
#pragma unroll
        for (int r = 0; r < KOUT; r++) {
            float md = slot_d; int ml = lane;
#pragma unroll
            for (int off = 16; off; off >>= 1) {
                float od = __shfl_xor_sync(0xffffffffu, md, off);
                int   ol = __shfl_xor_sync(0xffffffffu, ml, off);
                if (od < md || (od == md && ol < ml)) { md = od; ml = ol; }
            }
            if (lane == ml) {
                out[((size_t)b*nq + q)*KOUT + r] = slot_i;
                slot_d = 3.4e38f;                      // exclude from next round
            }
        }
    }
}

// ---------------- conv_surface (fm0) ----------------------------------------
__global__ void conv_surface_kernel(const float* __restrict__ verts,
                                    const int* __restrict__ nb,
                                    const float* __restrict__ dn0,
                                    float* __restrict__ fm0)
{
    int bv = blockIdx.x;
    int b = bv >> 12, v = bv & (NV-1);
    const float* vb = verts + (size_t)b*NV*3;
    __shared__ float sdx[KNN], sdy[KNN], sdz[KNN];
    int t = threadIdx.x;
    float cx = vb[v*3+0], cy = vb[v*3+1], cz = vb[v*3+2];
    if (t < KNN) {
        int j = nb[(size_t)bv*KNN + t];
        float dx = vb[j*3+0]-cx, dy = vb[j*3+1]-cy, dz = vb[j*3+2]-cz;
        float n = sqrtf(dx*dx+dy*dy+dz*dz);
        float inv = 1.0f / fmaxf(n, 1e-12f);
        sdx[t]=dx*inv; sdy[t]=dy*inv; sdz[t]=dz*inv;
    }
    __syncthreads();
    int k = t;
    float d0 = dn0[k], d1 = dn0[128+k], d2 = dn0[256+k];
    float m = 0.0f;
#pragma unroll
    for (int j=0;j<KNN;j++)
        m = fmaxf(m, sdx[j]*d0 + sdy[j]*d1 + sdz[j]*d2);
    fm0[(size_t)bv*128 + k] = m;
}

// ---------------- conv_layer epilogue (dirs prenormalized) -------------------
template<int COUT, bool RELU>
__global__ void conv_layer_kernel(const float* __restrict__ verts, int V,
                                  const int* __restrict__ nb,
                                  const float* __restrict__ f,
                                  const float* __restrict__ dn,
                                  float* __restrict__ out)
{
    int bv = blockIdx.x;
    int b = bv / V, v = bv - b*V;
    const float* vb = verts + (size_t)b*V*3;
    __shared__ float sdx[KNN], sdy[KNN], sdz[KNN];
    __shared__ int   si[KNN];
    int t = threadIdx.x;
    float cx = vb[v*3+0], cy = vb[v*3+1], cz = vb[v*3+2];
    if (t < KNN) {
        int j = nb[(size_t)bv*KNN + t];
        si[t] = j;
        float dx = vb[j*3+0]-cx, dy = vb[j*3+1]-cy, dz = vb[j*3+2]-cz;
        float n = sqrtf(dx*dx+dy*dy+dz*dz);
        float inv = 1.0f / fmaxf(n, 1e-12f);
        sdx[t]=dx*inv; sdy[t]=dy*inv; sdz[t]=dz*inv;
    }
    __syncthreads();
    const float* fb = f + (size_t)b*V*(2*COUT);
    for (int co = t; co < COUT; co += blockDim.x) {
        float d0 = dn[co], d1 = dn[COUT+co], d2 = dn[2*COUT+co];
        float m = -3.4e38f;
#pragma unroll 8
        for (int j=0;j<KNN;j++) {
            float th = fmaxf(sdx[j]*d0 + sdy[j]*d1 + sdz[j]*d2, 0.0f);
            float val = th * fb[si[j]*(2*COUT) + COUT + co];
            m = fmaxf(m, val);
        }
        float r = fb[v*(2*COUT) + co] + m;
        out[((size_t)b*V+v)*COUT + co] = RELU ? fmaxf(r, 0.0f) : r;
    }
}

// ---------------- pool ------------------------------------------------------
__global__ void pool_kernel(const float* __restrict__ verts,
                            const float* __restrict__ fm,
                            int V, int C,
                            const int* __restrict__ sidx,
                            const int* __restrict__ nb4, int ns,
                            float* __restrict__ vout, float* __restrict__ fout)
{
    int bq = blockIdx.x;
    int b = bq / ns, q = bq - b*ns;
    int t = threadIdx.x;
    int sv = sidx[q];
    if (t < 3) vout[(size_t)bq*3 + t] = verts[((size_t)b*V + sv)*3 + t];
    const int* nbq = nb4 + (size_t)bq*4;
    int j0=nbq[0], j1=nbq[1], j2=nbq[2], j3=nbq[3];
    const float* fb = fm + (size_t)b*V*C;
    for (int c=t; c<C; c+=blockDim.x) {
        float m = fmaxf(fmaxf(fb[j0*C+c], fb[j1*C+c]),
                        fmaxf(fb[j2*C+c], fb[j3*C+c]));
        fout[(size_t)bq*C + c] = m;
    }
}

// ---------------- nearest ---------------------------------------------------
__global__ void nearest_kernel(const float* __restrict__ verts,
                               const float* __restrict__ src,
                               int V, int S, int* __restrict__ out)
{
    int b = blockIdx.y;
    int q = blockIdx.x * 128 + threadIdx.x;
    const float* vb = verts + (size_t)b*V*3;
    const float* sb = src + (size_t)b*S*3;
    float qx = vb[q*3+0], qy = vb[q*3+1], qz = vb[q*3+2];
    float qa2 = qx*qx + qy*qy + qz*qz;
    float best = 3.4e38f; int bi = 0;
    __shared__ float4 sp[128];
    for (int t0=0; t0<S; t0+=128) {
        int j = t0 + threadIdx.x;
        float x = sb[j*3+0], y = sb[j*3+1], z = sb[j*3+2];
        sp[threadIdx.x] = make_float4(x,y,z, x*x+y*y+z*z);
        __syncthreads();
        for (int jj=0; jj<128; jj++) {
            float4 p = sp[jj];
            float d = qa2 + p.w - 2.0f*(qx*p.x + qy*p.y + qz*p.z);
            if (d < best) { best = d; bi = t0+jj; }
        }
        __syncthreads();
    }
    out[(size_t)b*V + q] = bi;
}

// ---------------- global feature --------------------------------------------
__global__ void fglobal_kernel(const float* __restrict__ fm4, float* __restrict__ g)
{
    int b = blockIdx.x, c = threadIdx.x;
    float m = -3.4e38f;
    for (int v=0; v<NP2; v++) m = fmaxf(m, fm4[((size_t)b*NP2+v)*512 + c]);
    g[(size_t)b*512 + c] = m;
}

// ---------------- fuse assembly -> bf16 hi/lo ---------------------------------
__global__ void fuse_kernel(const float* __restrict__ fm0, const float* __restrict__ fm1,
                            const float* __restrict__ fm2, const float* __restrict__ fm3,
                            const float* __restrict__ fm4, const float* __restrict__ fg,
                            const int* __restrict__ near1, const int* __restrict__ near2,
                            bf16* __restrict__ fhi, bf16* __restrict__ flo)
{
    int bv = blockIdx.x;
    int b = bv >> 12;
    int n1 = near1[bv], n2 = near2[bv];
    size_t o = (size_t)bv*1792;
    for (int c = threadIdx.x; c < 1792; c += blockDim.x) {
        float val;
        if (c < 128)        val = fm0[(size_t)bv*128 + c];
        else if (c < 256)   val = fm1[(size_t)bv*128 + (c-128)];
        else if (c < 512)   val = fm2[((size_t)b*NP1+n1)*256 + (c-256)];
        else if (c < 768)   val = fm3[((size_t)b*NP1+n1)*256 + (c-512)];
        else if (c < 1280)  val = fm4[((size_t)b*NP2+n2)*512 + (c-768)];
        else                val = fg [(size_t)b*512 + (c-1280)];
        bf16 h = __float2bfloat16(val);
        fhi[o+c] = h;
        flo[o+c] = __float2bfloat16(val - __bfloat162float(h));
    }
}

// ---------------- head: out(16 rows x 13) = h2 @ cw3^T + cb3 ----------------
__global__ void head_kernel(const float* __restrict__ h2,
                            const float* __restrict__ cw3,
                            const float* __restrict__ cb3,
                            float* __restrict__ out)
{
    __shared__ float sh[16][512];
    __shared__ float sw[13*513];
    const int tid = threadIdx.x;
    const int r = tid >> 4, c = tid & 15;
    const int row0 = blockIdx.x * 16;
    for (int i = tid; i < 16*512; i += 256)
        sh[i>>9][i&511] = h2[(size_t)row0*512 + i];
    for (int i = tid; i < 13*512; i += 256)
        sw[(i>>9)*513 + (i&511)] = cw3[i];
    __syncthreads();
    if (c < 13) {
        float acc = cb3[c];
        const float* w = &sw[c*513];
        const float* hrow = sh[r];
#pragma unroll 8
        for (int k=0;k<512;k++) acc += hrow[k]*w[k];
        out[(size_t)(row0+r)*13 + c] = acc;
    }
}

// -----------------------------------------------------------------------------
static void* sym_addr(const void* symbol) {
    void* p = nullptr;
    cudaGetSymbolAddress(&p, symbol);
    return p;
}

extern "C" void kernel_launch(void* const* d_in, const int* in_sizes, int n_in,
                              void* d_out, int out_size)
{
    (void)in_sizes; (void)n_in; (void)out_size;
    const float* vertices = (const float*)d_in[0];
    const int*   sidx1    = (const int*)  d_in[1];
    const int*   sidx2    = (const int*)  d_in[2];
    const float* dir0     = (const float*)d_in[3];
    const float* w1 = (const float*)d_in[4];  const float* b1 = (const float*)d_in[5];  const float* d1 = (const float*)d_in[6];
    const float* w2 = (const float*)d_in[7];  const float* b2 = (const float*)d_in[8];  const float* d2 = (const float*)d_in[9];
    const float* w3 = (const float*)d_in[10]; const float* b3 = (const float*)d_in[11]; const float* d3 = (const float*)d_in[12];
    const float* w4 = (const float*)d_in[13]; const float* b4 = (const float*)d_in[14]; const float* d4 = (const float*)d_in[15];
    const float* cw1 = (const float*)d_in[16]; const float* cb1 = (const float*)d_in[17];
    const float* cw2 = (const float*)d_in[18]; const float* cb2 = (const float*)d_in[19];
    const float* cw3 = (const float*)d_in[20]; const float* cb3 = (const float*)d_in[21];
    float* out = (float*)d_out;

    int*   nb1   = (int*)  sym_addr(g_nb1);
    int*   nb2   = (int*)  sym_addr(g_nb2);
    int*   nb3   = (int*)  sym_addr(g_nb3);
    int*   nbp   = (int*)  sym_addr(g_nbp);
    int*   near1 = (int*)  sym_addr(g_near1);
    int*   near2 = (int*)  sym_addr(g_near2);
    float* fm0   = (float*)sym_addr(g_fm0);
    float* fm1   = (float*)sym_addr(g_fm1);
    float* fbuf  = (float*)sym_addr(g_f);
    float* vp1   = (float*)sym_addr(g_vp1);
    float* fmp1  = (float*)sym_addr(g_fmp1);
    float* fm2   = (float*)sym_addr(g_fm2);
    float* fm3   = (float*)sym_addr(g_fm3);
    float* vp2   = (float*)sym_addr(g_vp2);
    float* fmp2  = (float*)sym_addr(g_fmp2);
    float* fm4   = (float*)sym_addr(g_fm4);
    float* fglob = (float*)sym_addr(g_fglob);
    float* h2    = (float*)sym_addr(g_h2);
    bf16* fusehi = (bf16*)sym_addr(g_fusehi);
    bf16* fuselo = (bf16*)sym_addr(g_fuselo);
    bf16* h1hi   = (bf16*)sym_addr(g_h1hi);
    bf16* h1lo   = (bf16*)sym_addr(g_h1lo);
    bf16* cw1hi  = (bf16*)sym_addr(g_cw1hi);
    bf16* cw1lo  = (bf16*)sym_addr(g_cw1lo);
    bf16* cw2hi  = (bf16*)sym_addr(g_cw2hi);
    bf16* cw2lo  = (bf16*)sym_addr(g_cw2lo);
    bf16* fm0hi  = (bf16*)sym_addr(g_fm0hi);   bf16* fm0lo  = (bf16*)sym_addr(g_fm0lo);
    bf16* fmp1hi = (bf16*)sym_addr(g_fmp1hi);  bf16* fmp1lo = (bf16*)sym_addr(g_fmp1lo);
    bf16* fm2hi  = (bf16*)sym_addr(g_fm2hi);   bf16* fm2lo  = (bf16*)sym_addr(g_fm2lo);
    bf16* fmp2hi = (bf16*)sym_addr(g_fmp2hi);  bf16* fmp2lo = (bf16*)sym_addr(g_fmp2lo);
    bf16* w1thi  = (bf16*)sym_addr(g_w1thi);   bf16* w1tlo  = (bf16*)sym_addr(g_w1tlo);
    bf16* w2thi  = (bf16*)sym_addr(g_w2thi);   bf16* w2tlo  = (bf16*)sym_addr(g_w2tlo);
    bf16* w3thi  = (bf16*)sym_addr(g_w3thi);   bf16* w3tlo  = (bf16*)sym_addr(g_w3tlo);
    bf16* w4thi  = (bf16*)sym_addr(g_w4thi);   bf16* w4tlo  = (bf16*)sym_addr(g_w4tlo);
    float* dn0 = (float*)sym_addr(g_dn0);
    float* dn1 = (float*)sym_addr(g_dn1);
    float* dn2 = (float*)sym_addr(g_dn2);
    float* dn3 = (float*)sym_addr(g_dn3);
    float* dn4 = (float*)sym_addr(g_dn4);

    cudaFuncSetAttribute(mma_gemm<1792,true,true>,  cudaFuncAttributeMaxDynamicSharedMemorySize, MMA_SMEM_TOTAL);
    cudaFuncSetAttribute(mma_gemm<512,true,false>,  cudaFuncAttributeMaxDynamicSharedMemorySize, MMA_SMEM_TOTAL);
    cudaFuncSetAttribute(mma_gemm<128,false,false>, cudaFuncAttributeMaxDynamicSharedMemorySize, MMA_SMEM_TOTAL);
    cudaFuncSetAttribute(mma_gemm<256,false,false>, cudaFuncAttributeMaxDynamicSharedMemorySize, MMA_SMEM_TOTAL);

    // idx0-2: weight splits + one ndirs, so knn_warp lands at PROFILED index 3
    split_kernel<<<(512*1792+255)/256, 256>>>(cw1, cw1hi, cw1lo, 512*1792);
    split_kernel<<<(512*512+255)/256, 256>>>(cw2, cw2hi, cw2lo, 512*512);
    ndirs_kernel<<<1, 128>>>(dir0, dn0, 128);
    // idx3: full-res KNN(32), warp-per-query  <-- ncu capture target
    knn_warp<32><<<dim3(NV/8, BSZ), 256>>>(vertices, nullptr, NV, NV, nb1);
    // remaining prep (tiny)
    ndirs_kernel<<<1, 128>>>(d1, dn1, 128);
    ndirs_kernel<<<2, 128>>>(d2, dn2, 256);
    ndirs_kernel<<<2, 128>>>(d3, dn3, 256);
    ndirs_kernel<<<4, 128>>>(d4, dn4, 512);
    tsplit_kernel<<<256, 128>>>(w1, 128, 256, w1thi, w1tlo);
    tsplit_kernel<<<512, 128>>>(w2, 128, 512, w2thi, w2tlo);
    tsplit_kernel<<<512, 256>>>(w3, 256, 512, w3thi, w3tlo);
    tsplit_kernel<<<1024, 256>>>(w4, 256, 1024, w4thi, w4tlo);
    // fm0 = conv_surface
    conv_surface_kernel<<<BSZ*NV, 128>>>(vertices, nb1, dn0, fm0);
    split_kernel<<<(BSZ*NV*128+255)/256, 256>>>(fm0, fm0hi, fm0lo, BSZ*NV*128);
    // fm1 = relu(conv_layer(fm0; w1,b1,d1; 128))
    mma_gemm<128,false,false><<<dim3(2, (BSZ*NV)/128), 512, MMA_SMEM_TOTAL>>>(
        fm0hi, fm0lo, w1thi, w1tlo, b1, 256, fbuf, nullptr, nullptr);
    conv_layer_kernel<128,true><<<BSZ*NV, 128>>>(vertices, NV, nb1, fbuf, dn1, fm1);
    // pool1
    knn_warp<4><<<dim3(NP1/8, BSZ), 256>>>(vertices, sidx1, NP1, NV, nbp);
    pool_kernel<<<BSZ*NP1, 128>>>(vertices, fm1, NV, 128, sidx1, nbp, NP1, vp1, fmp1);
    split_kernel<<<(BSZ*NP1*128+255)/256, 256>>>(fmp1, fmp1hi, fmp1lo, BSZ*NP1*128);
    // KNN level 1
    knn_warp<32><<<dim3(NP1/8, BSZ), 256>>>(vp1, nullptr, NP1, NP1, nb2);
    // fm2
    mma_gemm<128,false,false><<<dim3(4, (BSZ*NP1)/128), 512, MMA_SMEM_TOTAL>>>(
        fmp1hi, fmp1lo, w2thi, w2tlo, b2, 512, fbuf, nullptr, nullptr);
    conv_layer_kernel<256,true><<<BSZ*NP1, 256>>>(vp1, NP1, nb2, fbuf, dn2, fm2);
    split_kernel<<<(BSZ*NP1*256+255)/256, 256>>>(fm2, fm2hi, fm2lo, BSZ*NP1*256);
    // fm3
    mma_gemm<256,false,false><<<dim3(4, (BSZ*NP1)/128), 512, MMA_SMEM_TOTAL>>>(
        fm2hi, fm2lo, w3thi, w3tlo, b3, 512, fbuf, nullptr, nullptr);
    conv_layer_kernel<256,true><<<BSZ*NP1, 256>>>(vp1, NP1, nb2, fbuf, dn3, fm3);
    // pool2
    knn_warp<4><<<dim3(NP2/8, BSZ), 256>>>(vp1, sidx2, NP2, NP1, nbp);
    pool_kernel<<<BSZ*NP2, 256>>>(vp1, fm3, NP1, 256, sidx2, nbp, NP2, vp2, fmp2);
    split_kernel<<<(BSZ*NP2*256+255)/256, 256>>>(fmp2, fmp2hi, fmp2lo, BSZ*NP2*256);
    // KNN level 2
    knn_warp<32><<<dim3(NP2/8, BSZ), 256>>>(vp2, nullptr, NP2, NP2, nb3);
    // fm4
    mma_gemm<256,false,false><<<dim3(8, (BSZ*NP2)/128), 512, MMA_SMEM_TOTAL>>>(
        fmp2hi, fmp2lo, w4thi, w4tlo, b4, 1024, fbuf, nullptr, nullptr);
    conv_layer_kernel<512,false><<<BSZ*NP2, 256>>>(vp2, NP2, nb3, fbuf, dn4, fm4);
    // global max feature
    fglobal_kernel<<<BSZ, 512>>>(fm4, fglob);
    // nearest upsample indices
    nearest_kernel<<<dim3(NV/128, BSZ), 128>>>(vertices, vp1, NV, NP1, near1);
    nearest_kernel<<<dim3(NV/128, BSZ), 128>>>(vertices, vp2, NV, NP2, near2);
    // fuse -> bf16 hi/lo
    fuse_kernel<<<BSZ*NV, 256>>>(fm0, fm1, fm2, fm3, fm4, fglob, near1, near2, fusehi, fuselo);
    // h1 = relu(fuse @ cw1^T + cb1)
    mma_gemm<1792,true,true><<<dim3(4, (BSZ*NV)/128), 512, MMA_SMEM_TOTAL>>>(
        fusehi, fuselo, cw1hi, cw1lo, cb1, 512, nullptr, h1hi, h1lo);
    // h2 = relu(h1 @ cw2^T + cb2)
    mma_gemm<512,true,false><<<dim3(4, (BSZ*NV)/128), 512, MMA_SMEM_TOTAL>>>(
        h1hi, h1lo, cw2hi, cw2lo, cb2, 512, h2, nullptr, nullptr);
    // logits
    head_kernel<<<(BSZ*NV)/16, 256>>>(h2, cw3, cb3, out);
}